// round 10
// baseline (speedup 1.0000x reference)
#include <cuda_runtime.h>
#include <stdint.h>
#include <math.h>

#define H   256
#define EMAX 200000

// 204.8 MB scratch for the scatter-add target (allocation-free rule: static __device__).
__device__ float g_agg[(size_t)EMAX * H];
// Index dtype mode: 1 = int64, 0 = int32.
__device__ int g_idx_mode;

__device__ __forceinline__ void mma_tf32(float c[4], const uint32_t a[4], const uint32_t b[2]) {
    asm volatile(
        "mma.sync.aligned.m16n8k8.row.col.f32.tf32.tf32.f32 "
        "{%0,%1,%2,%3},{%4,%5,%6,%7},{%8,%9},{%0,%1,%2,%3};"
        : "+f"(c[0]), "+f"(c[1]), "+f"(c[2]), "+f"(c[3])
        : "r"(a[0]), "r"(a[1]), "r"(a[2]), "r"(a[3]), "r"(b[0]), "r"(b[1]));
}

// ldmatrix x4: thread L receives, in reg j, matrix j's (row L>>2, 4B-word L&3).
// Lane L supplies the address of matrix (L>>3), row (L&7) — 16B aligned.
__device__ __forceinline__ void ldsm_x4(uint32_t& r0, uint32_t& r1, uint32_t& r2, uint32_t& r3,
                                        uint32_t addr) {
    asm volatile("ldmatrix.sync.aligned.m8n8.x4.shared.b16 {%0,%1,%2,%3}, [%4];"
                 : "=r"(r0), "=r"(r1), "=r"(r2), "=r"(r3) : "r"(addr));
}

__device__ __forceinline__ float sigmoidf_(float x) {
    return 1.0f / (1.0f + __expf(-x));
}

__device__ __forceinline__ void cp16(uint32_t dst, const void* src, bool pred) {
    int sz = pred ? 16 : 0;
    asm volatile("cp.async.cg.shared.global [%0], [%1], 16, %2;\n"
                 :: "r"(dst), "l"(src), "r"(sz));
}
__device__ __forceinline__ void cp_commit() {
    asm volatile("cp.async.commit_group;\n");
}
template <int N>
__device__ __forceinline__ void cp_wait() {
    asm volatile("cp.async.wait_group %0;\n" :: "n"(N));
}

// ============================================================================
// Kernel A: detect index dtype (int64 vs int32 materialization of edge_index).
// ============================================================================
__global__ void detect_idx_kernel(const int* __restrict__ idx32)
{
    __shared__ int ored[256];
    int t = threadIdx.x;
    ored[t] = idx32[2 * t + 1];
    __syncthreads();
    for (int s = 128; s > 0; s >>= 1) {
        if (t < s) ored[t] |= ored[t + s];
        __syncthreads();
    }
    if (t == 0) g_idx_mode = (ored[0] == 0) ? 1 : 0;
}

// ============================================================================
// Kernel 0: zero the aggregation scratch.
// ============================================================================
__global__ void zero_agg_kernel(int total4)
{
    float4* p = reinterpret_cast<float4*>(g_agg);
    int idx = blockIdx.x * blockDim.x + threadIdx.x;
    int stride = gridDim.x * blockDim.x;
    float4 z = make_float4(0.f, 0.f, 0.f, 0.f);
    for (int i = idx; i < total4; i += stride) p[i] = z;
}

// ============================================================================
// Kernel 1 (UNCHANGED from round 9): relu(X @ W_msg^T + b) + atomic scatter.
// kchunk 32, 2-stage cp.async, y-fast grid, ldmatrix fragments.
// ============================================================================
#define MS_STAGE 6912

__global__ __launch_bounds__(256)
void msg_scatter_kernel(const float* __restrict__ X,
                        const void* __restrict__ eidx,
                        const float* __restrict__ W,
                        const float* __restrict__ bias,
                        int E)
{
    extern __shared__ uint32_t dsm[];
    __shared__ int dsts[128];

    const int tid  = threadIdx.x;
    const int lane = tid & 31;
    const int wid  = tid >> 5;
    const int wm   = wid & 3;
    const int wn   = wid >> 2;
    const int row0 = (int)(blockIdx.x >> 2) * 128;
    const int n0   = (int)(blockIdx.x & 3) * 64;
    const uint32_t sbase = (uint32_t)__cvta_generic_to_shared(dsm);

    const int sub  = lane >> 3;
    const int lrow = lane & 7;
    const int aoffw = ((sub & 1) * 8 + lrow) * 36 + (sub >> 1) * 4;
    const int boffw = ((sub >> 1) * 8 + lrow) * 36 + (sub & 1) * 4;

    if (tid < 128) {
        int r = row0 + tid;
        int d = -1;
        if (r < E) {
            d = g_idx_mode ? (int)((const long long*)eidx)[(size_t)E + r]
                           : ((const int*)eidx)[(size_t)E + r];
            if (d < 0 || d >= E) d = -1;
        }
        dsts[tid] = d;
    }

    const int lr  = tid >> 3;
    const int lc4 = (tid & 7) * 4;

    auto load_stage = [&](int st, int k0) {
        uint32_t sb = sbase + st * (MS_STAGE * 4);
#pragma unroll
        for (int p = 0; p < 4; p++) {
            int r  = p * 32 + lr;
            int gr = row0 + r;
            cp16(sb + (r * 36 + lc4) * 4, X + (size_t)gr * H + k0 + lc4, gr < E);
        }
#pragma unroll
        for (int p = 0; p < 2; p++) {
            int r = p * 32 + lr;
            cp16(sb + (4608 + r * 36 + lc4) * 4,
                 W + (size_t)(n0 + r) * H + k0 + lc4, true);
        }
        cp_commit();
    };

    float acc[2][4][4];
#pragma unroll
    for (int i = 0; i < 2; i++)
#pragma unroll
        for (int j = 0; j < 4; j++)
#pragma unroll
            for (int k = 0; k < 4; k++) acc[i][j][k] = 0.0f;

    load_stage(0, 0);

    for (int kc = 0; kc < 8; kc++) {
        if (kc < 7) { load_stage((kc + 1) & 1, (kc + 1) * 32); cp_wait<1>(); }
        else        { cp_wait<0>(); }
        __syncthreads();

        const uint32_t Au = sbase + ((kc & 1) * MS_STAGE) * 4;
        const uint32_t Bu = Au + 4608 * 4;

#pragma unroll
        for (int ks = 0; ks < 4; ks++) {
            int kk = ks * 8;
            uint32_t a[2][4], b[4][2];
#pragma unroll
            for (int mi = 0; mi < 2; mi++)
                ldsm_x4(a[mi][0], a[mi][1], a[mi][2], a[mi][3],
                        Au + (aoffw + (wm * 32 + mi * 16) * 36 + kk) * 4);
#pragma unroll
            for (int np = 0; np < 2; np++)
                ldsm_x4(b[2 * np][0], b[2 * np][1], b[2 * np + 1][0], b[2 * np + 1][1],
                        Bu + (boffw + (wn * 32 + np * 16) * 36 + kk) * 4);
#pragma unroll
            for (int mi = 0; mi < 2; mi++)
#pragma unroll
                for (int ni = 0; ni < 4; ni++)
                    mma_tf32(acc[mi][ni], a[mi], b[ni]);
        }
        __syncthreads();
    }

#pragma unroll
    for (int mi = 0; mi < 2; mi++) {
#pragma unroll
        for (int half = 0; half < 2; half++) {
            int rl = wm * 32 + mi * 16 + (lane >> 2) + half * 8;
            int d  = dsts[rl];
            if (d < 0) continue;
            size_t base = (size_t)d * H;
#pragma unroll
            for (int ni = 0; ni < 4; ni++) {
                int col  = n0 + wn * 32 + ni * 8 + 2 * (lane & 3);
                float v0 = fmaxf(acc[mi][ni][half * 2 + 0] + __ldg(&bias[col]), 0.0f);
                float v1 = fmaxf(acc[mi][ni][half * 2 + 1] + __ldg(&bias[col + 1]), 0.0f);
                atomicAdd(&g_agg[base + col],     v0);
                atomicAdd(&g_agg[base + col + 1], v1);
            }
        }
    }
}

// ============================================================================
// Kernel 2: GRU fused GEMMs — ONE 768-thread block per 128-row tile.
// 24 warps = (wm 0..3 row-slab, g 0..5 gate); warp tile 32x32 (same per-warp
// work/registers as round 9). 3-stage cp.async ring, kchunk 32, ONE sync/chunk.
// Benefits vs 2x384: B stage writes + B L2 reads halved, syncs per 128 rows
// 4 -> 1. Stage (words): Aagg[128*36]@0, Ax@4608, B[192*36]@9216 = 16128.
// gbuf (128x192 fp32 = 98KB) aliases the 193.5KB ring after the mainloop.
// ============================================================================
#define GK_STAGE   16128
#define GK_THREADS 768

__global__ __launch_bounds__(GK_THREADS, 1)
void gru_kernel(const float* __restrict__ X,
                const float* __restrict__ Wih,
                const float* __restrict__ Whh,
                const float* __restrict__ bih,
                const float* __restrict__ bhh,
                float* __restrict__ out,
                int E)
{
    extern __shared__ uint32_t dsm[];
    float* gbuf = reinterpret_cast<float*>(dsm);

    const int tid  = threadIdx.x;
    const int lane = tid & 31;
    const int wid  = tid >> 5;
    const int wm   = wid & 3;                      // row slab 0..3
    const int g    = wid >> 2;                     // gate 0..5
    const int row0 = (int)(blockIdx.x >> 3) * 128; // y-fast: low 3 bits = n-tile
    const int n0   = (int)(blockIdx.x & 7) * 32;
    const uint32_t sbase = (uint32_t)__cvta_generic_to_shared(dsm);

    const int sub  = lane >> 3;
    const int lrow = lane & 7;
    const int aoffw = ((sub & 1) * 8 + lrow) * 36 + (sub >> 1) * 4;
    const int boffw = ((sub >> 1) * 8 + lrow) * 36 + (sub & 1) * 4;

    auto load_stage = [&](int st, int k0) {
        uint32_t sb = sbase + st * (GK_STAGE * 4);
        // A tiles: agg (128x32) then X (128x32): 2048 16B-chunks
        for (int f = tid; f < 2048; f += GK_THREADS) {
            int which = f >> 10;
            int rem   = f & 1023;
            int r     = rem >> 3;
            int c4    = (rem & 7) * 4;
            int gr    = row0 + r;
            const float* src = which ? (X + (size_t)gr * H)
                                     : (g_agg + (size_t)gr * H);
            cp16(sb + ((which ? 4608 : 0) + r * 36 + c4) * 4,
                 src + k0 + c4, gr < E);
        }
        // 6 weight tiles (32x32 each): 1536 16B-chunks (2/thread)
#pragma unroll
        for (int q = 0; q < 2; q++) {
            int f   = tid + q * GK_THREADS;
            int g2  = f >> 8;
            int rem = f & 255;
            int r   = rem >> 3;
            int c4  = (rem & 7) * 4;
            int gate = (g2 < 3) ? g2 : (g2 - 3);
            const float* Wsrc = (g2 < 3) ? Wih : Whh;
            cp16(sb + (9216 + (g2 * 32 + r) * 36 + c4) * 4,
                 Wsrc + (size_t)(gate * H + n0 + r) * H + k0 + c4, true);
        }
        cp_commit();
    };

    float acc[2][4][4];
#pragma unroll
    for (int i = 0; i < 2; i++)
#pragma unroll
        for (int j = 0; j < 4; j++)
#pragma unroll
            for (int k = 0; k < 4; k++) acc[i][j][k] = 0.0f;

    load_stage(0, 0);
    load_stage(1, 32);

    for (int kc = 0; kc < 8; kc++) {
        if (kc < 7) cp_wait<1>(); else cp_wait<0>();
        __syncthreads();   // separates all reads of buf (kc-1)%3 from its rewrite below
        if (kc + 2 < 8) load_stage((kc + 2) % 3, (kc + 2) * 32);

        const uint32_t Su = sbase + ((kc % 3) * GK_STAGE) * 4;
        const uint32_t Au = Su + ((g < 3) ? 0 : 4608) * 4;
        const uint32_t Bu = Su + 9216 * 4;

#pragma unroll
        for (int ks = 0; ks < 4; ks++) {
            int kk = ks * 8;
            uint32_t a[2][4], b[4][2];
#pragma unroll
            for (int mi = 0; mi < 2; mi++)
                ldsm_x4(a[mi][0], a[mi][1], a[mi][2], a[mi][3],
                        Au + (aoffw + (wm * 32 + mi * 16) * 36 + kk) * 4);
#pragma unroll
            for (int np = 0; np < 2; np++)
                ldsm_x4(b[2 * np][0], b[2 * np][1], b[2 * np + 1][0], b[2 * np + 1][1],
                        Bu + (boffw + (g * 32 + np * 16) * 36 + kk) * 4);
#pragma unroll
            for (int mi = 0; mi < 2; mi++)
#pragma unroll
                for (int ni = 0; ni < 4; ni++)
                    mma_tf32(acc[mi][ni], a[mi], b[ni]);
        }
    }

    __syncthreads();   // all warps done reading the ring before gbuf aliasing

    // ---- dump accumulators: gbuf[r][g*32 + c], rows 0..127, stride 192 ----
#pragma unroll
    for (int mi = 0; mi < 2; mi++) {
        int r = wm * 32 + mi * 16 + (lane >> 2);
#pragma unroll
        for (int ni = 0; ni < 4; ni++) {
            int c = g * 32 + ni * 8 + 2 * (lane & 3);
            gbuf[r * 192 + c]           = acc[mi][ni][0];
            gbuf[r * 192 + c + 1]       = acc[mi][ni][1];
            gbuf[(r + 8) * 192 + c]     = acc[mi][ni][2];
            gbuf[(r + 8) * 192 + c + 1] = acc[mi][ni][3];
        }
    }
    __syncthreads();

    // ---- GRU gate math + output (4096 elems / 768 threads) ----
    for (int idx = tid; idx < 128 * 32; idx += GK_THREADS) {
        int r  = idx >> 5;
        int c  = idx & 31;
        int gr = row0 + r;
        if (gr >= E) continue;
        int gc = n0 + c;
        const float* gr_ = &gbuf[r * 192];
        float i_r = gr_[c]       + __ldg(&bih[gc]);
        float i_z = gr_[32 + c]  + __ldg(&bih[H + gc]);
        float i_n = gr_[64 + c]  + __ldg(&bih[2 * H + gc]);
        float h_r = gr_[96 + c]  + __ldg(&bhh[gc]);
        float h_z = gr_[128 + c] + __ldg(&bhh[H + gc]);
        float h_n = gr_[160 + c] + __ldg(&bhh[2 * H + gc]);

        float rg = sigmoidf_(i_r + h_r);
        float z  = sigmoidf_(i_z + h_z);
        float n  = tanhf(i_n + rg * h_n);
        float hp = __ldg(&X[(size_t)gr * H + gc]);
        out[(size_t)gr * H + gc] = (1.0f - z) * n + z * hp;
    }
}

// ============================================================================
extern "C" void kernel_launch(void* const* d_in, const int* in_sizes, int n_in,
                              void* d_out, int out_size)
{
    const float* X   = (const float*)d_in[0];
    const void*  ei  = d_in[1];
    const float* Wm  = (const float*)d_in[2];
    const float* bm  = (const float*)d_in[3];
    const float* Wih = (const float*)d_in[4];
    const float* Whh = (const float*)d_in[5];
    const float* bih = (const float*)d_in[6];
    const float* bhh = (const float*)d_in[7];
    float*       out = (float*)d_out;

    int E = in_sizes[0] / H;

    cudaFuncSetAttribute(msg_scatter_kernel,
                         cudaFuncAttributeMaxDynamicSharedMemorySize, 2 * MS_STAGE * 4);
    cudaFuncSetAttribute(gru_kernel,
                         cudaFuncAttributeMaxDynamicSharedMemorySize, 3 * GK_STAGE * 4);

    detect_idx_kernel<<<1, 256>>>((const int*)ei);
    zero_agg_kernel<<<4096, 256>>>((E * H) / 4);

    int mrows = (E + 127) / 128;
    msg_scatter_kernel<<<mrows * 4, 256, 2 * MS_STAGE * 4>>>(X, ei, Wm, bm, E);

    int grows = (E + 127) / 128;
    gru_kernel<<<grows * 8, GK_THREADS, 3 * GK_STAGE * 4>>>(X, Wih, Whh, bih, bhh, out, E);
}

// round 11
// speedup vs baseline: 1.1077x; 1.1077x over previous
#include <cuda_runtime.h>
#include <stdint.h>
#include <math.h>

#define H   256
#define EMAX 200000

// 204.8 MB scratch for the scatter-add target (allocation-free rule: static __device__).
__device__ float g_agg[(size_t)EMAX * H];
// Index dtype mode: 1 = int64, 0 = int32.
__device__ int g_idx_mode;

__device__ __forceinline__ void mma_tf32(float c[4], const uint32_t a[4], const uint32_t b[2]) {
    asm volatile(
        "mma.sync.aligned.m16n8k8.row.col.f32.tf32.tf32.f32 "
        "{%0,%1,%2,%3},{%4,%5,%6,%7},{%8,%9},{%0,%1,%2,%3};"
        : "+f"(c[0]), "+f"(c[1]), "+f"(c[2]), "+f"(c[3])
        : "r"(a[0]), "r"(a[1]), "r"(a[2]), "r"(a[3]), "r"(b[0]), "r"(b[1]));
}

// ldmatrix x4: thread L receives, in reg j, matrix j's (row L>>2, 4B-word L&3).
__device__ __forceinline__ void ldsm_x4(uint32_t& r0, uint32_t& r1, uint32_t& r2, uint32_t& r3,
                                        uint32_t addr) {
    asm volatile("ldmatrix.sync.aligned.m8n8.x4.shared.b16 {%0,%1,%2,%3}, [%4];"
                 : "=r"(r0), "=r"(r1), "=r"(r2), "=r"(r3) : "r"(addr));
}

__device__ __forceinline__ float sigmoidf_(float x) {
    return 1.0f / (1.0f + __expf(-x));
}

__device__ __forceinline__ void cp16(uint32_t dst, const void* src, bool pred) {
    int sz = pred ? 16 : 0;
    asm volatile("cp.async.cg.shared.global [%0], [%1], 16, %2;\n"
                 :: "r"(dst), "l"(src), "r"(sz));
}
__device__ __forceinline__ void cp_commit() {
    asm volatile("cp.async.commit_group;\n");
}
template <int N>
__device__ __forceinline__ void cp_wait() {
    asm volatile("cp.async.wait_group %0;\n" :: "n"(N));
}

// ============================================================================
// Kernel A: detect index dtype (int64 vs int32 materialization of edge_index).
// ============================================================================
__global__ void detect_idx_kernel(const int* __restrict__ idx32)
{
    __shared__ int ored[256];
    int t = threadIdx.x;
    ored[t] = idx32[2 * t + 1];
    __syncthreads();
    for (int s = 128; s > 0; s >>= 1) {
        if (t < s) ored[t] |= ored[t + s];
        __syncthreads();
    }
    if (t == 0) g_idx_mode = (ored[0] == 0) ? 1 : 0;
}

// ============================================================================
// Kernel 0: zero the aggregation scratch.
// ============================================================================
__global__ void zero_agg_kernel(int total4)
{
    float4* p = reinterpret_cast<float4*>(g_agg);
    int idx = blockIdx.x * blockDim.x + threadIdx.x;
    int stride = gridDim.x * blockDim.x;
    float4 z = make_float4(0.f, 0.f, 0.f, 0.f);
    for (int i = idx; i < total4; i += stride) p[i] = z;
}

// ============================================================================
// Kernel 1: relu(X @ W_msg^T + b) + atomic scatter. Round-9 structure with
// ONE sync per chunk (wait<0> -> sync -> issue next load -> MMA) and
// float2 vector atomics in the epilogue.
// ============================================================================
#define MS_STAGE 6912

__global__ __launch_bounds__(256)
void msg_scatter_kernel(const float* __restrict__ X,
                        const void* __restrict__ eidx,
                        const float* __restrict__ W,
                        const float* __restrict__ bias,
                        int E)
{
    extern __shared__ uint32_t dsm[];
    __shared__ int dsts[128];

    const int tid  = threadIdx.x;
    const int lane = tid & 31;
    const int wid  = tid >> 5;
    const int wm   = wid & 3;
    const int wn   = wid >> 2;
    const int row0 = (int)(blockIdx.x >> 2) * 128;
    const int n0   = (int)(blockIdx.x & 3) * 64;
    const uint32_t sbase = (uint32_t)__cvta_generic_to_shared(dsm);

    const int sub  = lane >> 3;
    const int lrow = lane & 7;
    const int aoffw = ((sub & 1) * 8 + lrow) * 36 + (sub >> 1) * 4;
    const int boffw = ((sub >> 1) * 8 + lrow) * 36 + (sub & 1) * 4;

    if (tid < 128) {
        int r = row0 + tid;
        int d = -1;
        if (r < E) {
            d = g_idx_mode ? (int)((const long long*)eidx)[(size_t)E + r]
                           : ((const int*)eidx)[(size_t)E + r];
            if (d < 0 || d >= E) d = -1;
        }
        dsts[tid] = d;
    }

    const int lr  = tid >> 3;
    const int lc4 = (tid & 7) * 4;

    auto load_stage = [&](int st, int k0) {
        uint32_t sb = sbase + st * (MS_STAGE * 4);
#pragma unroll
        for (int p = 0; p < 4; p++) {
            int r  = p * 32 + lr;
            int gr = row0 + r;
            cp16(sb + (r * 36 + lc4) * 4, X + (size_t)gr * H + k0 + lc4, gr < E);
        }
#pragma unroll
        for (int p = 0; p < 2; p++) {
            int r = p * 32 + lr;
            cp16(sb + (4608 + r * 36 + lc4) * 4,
                 W + (size_t)(n0 + r) * H + k0 + lc4, true);
        }
        cp_commit();
    };

    float acc[2][4][4];
#pragma unroll
    for (int i = 0; i < 2; i++)
#pragma unroll
        for (int j = 0; j < 4; j++)
#pragma unroll
            for (int k = 0; k < 4; k++) acc[i][j][k] = 0.0f;

    load_stage(0, 0);

    for (int kc = 0; kc < 8; kc++) {
        cp_wait<0>();          // only load(kc) outstanding here
        __syncthreads();       // all warps done reading buf (kc+1)&1 (iter kc-1)
        if (kc < 7) load_stage((kc + 1) & 1, (kc + 1) * 32);

        const uint32_t Au = sbase + ((kc & 1) * MS_STAGE) * 4;
        const uint32_t Bu = Au + 4608 * 4;

#pragma unroll
        for (int ks = 0; ks < 4; ks++) {
            int kk = ks * 8;
            uint32_t a[2][4], b[4][2];
#pragma unroll
            for (int mi = 0; mi < 2; mi++)
                ldsm_x4(a[mi][0], a[mi][1], a[mi][2], a[mi][3],
                        Au + (aoffw + (wm * 32 + mi * 16) * 36 + kk) * 4);
#pragma unroll
            for (int np = 0; np < 2; np++)
                ldsm_x4(b[2 * np][0], b[2 * np][1], b[2 * np + 1][0], b[2 * np + 1][1],
                        Bu + (boffw + (wn * 32 + np * 16) * 36 + kk) * 4);
#pragma unroll
            for (int mi = 0; mi < 2; mi++)
#pragma unroll
                for (int ni = 0; ni < 4; ni++)
                    mma_tf32(acc[mi][ni], a[mi], b[ni]);
        }
    }

    // ---- epilogue: bias + relu + float2 vector atomics ----
#pragma unroll
    for (int mi = 0; mi < 2; mi++) {
#pragma unroll
        for (int half = 0; half < 2; half++) {
            int rl = wm * 32 + mi * 16 + (lane >> 2) + half * 8;
            int d  = dsts[rl];
            if (d < 0) continue;
            size_t base = (size_t)d * H;
#pragma unroll
            for (int ni = 0; ni < 4; ni++) {
                int col  = n0 + wn * 32 + ni * 8 + 2 * (lane & 3);   // even -> 8B aligned
                float v0 = fmaxf(acc[mi][ni][half * 2 + 0] + __ldg(&bias[col]), 0.0f);
                float v1 = fmaxf(acc[mi][ni][half * 2 + 1] + __ldg(&bias[col + 1]), 0.0f);
                atomicAdd(reinterpret_cast<float2*>(&g_agg[base + col]),
                          make_float2(v0, v1));
            }
        }
    }
}

// ============================================================================
// Kernel 2: GRU fused GEMMs — round-9 shape (384 thr, 2 blocks/SM,
// warp=(row-half, gate), kchunk 32, 2-stage) with ONE sync per chunk.
// ============================================================================
#define GK_STAGE 11520

__global__ __launch_bounds__(384, 2)
void gru_kernel(const float* __restrict__ X,
                const float* __restrict__ Wih,
                const float* __restrict__ Whh,
                const float* __restrict__ bih,
                const float* __restrict__ bhh,
                float* __restrict__ out,
                int E)
{
    extern __shared__ uint32_t dsm[];
    float* gbuf = reinterpret_cast<float*>(dsm);

    const int tid  = threadIdx.x;
    const int lane = tid & 31;
    const int wid  = tid >> 5;
    const int wm   = wid & 1;
    const int g    = wid >> 1;
    const int row0 = (int)(blockIdx.x >> 3) * 64;
    const int n0   = (int)(blockIdx.x & 7) * 32;
    const uint32_t sbase = (uint32_t)__cvta_generic_to_shared(dsm);

    const int sub  = lane >> 3;
    const int lrow = lane & 7;
    const int aoffw = ((sub & 1) * 8 + lrow) * 36 + (sub >> 1) * 4;
    const int boffw = ((sub >> 1) * 8 + lrow) * 36 + (sub & 1) * 4;

    auto load_stage = [&](int st, int k0) {
        uint32_t sb = sbase + st * (GK_STAGE * 4);
        for (int f = tid; f < 1024; f += 384) {
            int which = f >> 9;
            int rem   = f & 511;
            int r     = rem >> 3;
            int c4    = (rem & 7) * 4;
            int gr    = row0 + r;
            const float* src = which ? (X + (size_t)gr * H)
                                     : (g_agg + (size_t)gr * H);
            cp16(sb + ((which ? 2304 : 0) + r * 36 + c4) * 4,
                 src + k0 + c4, gr < E);
        }
#pragma unroll
        for (int q = 0; q < 4; q++) {
            int f   = tid + q * 384;
            int g2  = f >> 8;
            int rem = f & 255;
            int r   = rem >> 3;
            int c4  = (rem & 7) * 4;
            int gate = (g2 < 3) ? g2 : (g2 - 3);
            const float* Wsrc = (g2 < 3) ? Wih : Whh;
            cp16(sb + (4608 + (g2 * 32 + r) * 36 + c4) * 4,
                 Wsrc + (size_t)(gate * H + n0 + r) * H + k0 + c4, true);
        }
        cp_commit();
    };

    float acc[2][4][4];
#pragma unroll
    for (int i = 0; i < 2; i++)
#pragma unroll
        for (int j = 0; j < 4; j++)
#pragma unroll
            for (int k = 0; k < 4; k++) acc[i][j][k] = 0.0f;

    load_stage(0, 0);

    for (int kc = 0; kc < 8; kc++) {
        cp_wait<0>();          // only load(kc) outstanding here
        __syncthreads();       // all warps done reading buf (kc+1)&1 (iter kc-1)
        if (kc < 7) load_stage((kc + 1) & 1, (kc + 1) * 32);

        const uint32_t Su = sbase + ((kc & 1) * GK_STAGE) * 4;
        const uint32_t Au = Su + ((g < 3) ? 0 : 2304) * 4;
        const uint32_t Bu = Su + 4608 * 4;

#pragma unroll
        for (int ks = 0; ks < 4; ks++) {
            int kk = ks * 8;
            uint32_t a[2][4], b[4][2];
#pragma unroll
            for (int mi = 0; mi < 2; mi++)
                ldsm_x4(a[mi][0], a[mi][1], a[mi][2], a[mi][3],
                        Au + (aoffw + (wm * 32 + mi * 16) * 36 + kk) * 4);
#pragma unroll
            for (int np = 0; np < 2; np++)
                ldsm_x4(b[2 * np][0], b[2 * np][1], b[2 * np + 1][0], b[2 * np + 1][1],
                        Bu + (boffw + (g * 32 + np * 16) * 36 + kk) * 4);
#pragma unroll
            for (int mi = 0; mi < 2; mi++)
#pragma unroll
                for (int ni = 0; ni < 4; ni++)
                    mma_tf32(acc[mi][ni], a[mi], b[ni]);
        }
    }

    __syncthreads();   // all warps done reading the ring before gbuf aliasing

    // ---- dump accumulators: gbuf[r][g*32 + c], row stride 192, float2 ----
#pragma unroll
    for (int mi = 0; mi < 2; mi++) {
        int r = wm * 32 + mi * 16 + (lane >> 2);
#pragma unroll
        for (int ni = 0; ni < 4; ni++) {
            int c = g * 32 + ni * 8 + 2 * (lane & 3);
            *reinterpret_cast<float2*>(&gbuf[r * 192 + c]) =
                make_float2(acc[mi][ni][0], acc[mi][ni][1]);
            *reinterpret_cast<float2*>(&gbuf[(r + 8) * 192 + c]) =
                make_float2(acc[mi][ni][2], acc[mi][ni][3]);
        }
    }
    __syncthreads();

    // ---- GRU gate math + output ----
    for (int idx = tid; idx < 64 * 32; idx += 384) {
        int r  = idx >> 5;
        int c  = idx & 31;
        int gr = row0 + r;
        if (gr >= E) continue;
        int gc = n0 + c;
        const float* gr_ = &gbuf[r * 192];
        float i_r = gr_[c]       + __ldg(&bih[gc]);
        float i_z = gr_[32 + c]  + __ldg(&bih[H + gc]);
        float i_n = gr_[64 + c]  + __ldg(&bih[2 * H + gc]);
        float h_r = gr_[96 + c]  + __ldg(&bhh[gc]);
        float h_z = gr_[128 + c] + __ldg(&bhh[H + gc]);
        float h_n = gr_[160 + c] + __ldg(&bhh[2 * H + gc]);

        float rg = sigmoidf_(i_r + h_r);
        float z  = sigmoidf_(i_z + h_z);
        float n  = tanhf(i_n + rg * h_n);
        float hp = __ldg(&X[(size_t)gr * H + gc]);
        out[(size_t)gr * H + gc] = (1.0f - z) * n + z * hp;
    }
}

// ============================================================================
extern "C" void kernel_launch(void* const* d_in, const int* in_sizes, int n_in,
                              void* d_out, int out_size)
{
    const float* X   = (const float*)d_in[0];
    const void*  ei  = d_in[1];
    const float* Wm  = (const float*)d_in[2];
    const float* bm  = (const float*)d_in[3];
    const float* Wih = (const float*)d_in[4];
    const float* Whh = (const float*)d_in[5];
    const float* bih = (const float*)d_in[6];
    const float* bhh = (const float*)d_in[7];
    float*       out = (float*)d_out;

    int E = in_sizes[0] / H;

    cudaFuncSetAttribute(msg_scatter_kernel,
                         cudaFuncAttributeMaxDynamicSharedMemorySize, 2 * MS_STAGE * 4);
    cudaFuncSetAttribute(gru_kernel,
                         cudaFuncAttributeMaxDynamicSharedMemorySize, 2 * GK_STAGE * 4);

    detect_idx_kernel<<<1, 256>>>((const int*)ei);
    zero_agg_kernel<<<4096, 256>>>((E * H) / 4);

    int mrows = (E + 127) / 128;
    msg_scatter_kernel<<<mrows * 4, 256, 2 * MS_STAGE * 4>>>(X, ei, Wm, bm, E);

    int grows = (E + 63) / 64;
    gru_kernel<<<grows * 8, 384, 2 * GK_STAGE * 4>>>(X, Wih, Whh, bih, bhh, out, E);
}

// round 12
// speedup vs baseline: 1.2443x; 1.1233x over previous
#include <cuda_runtime.h>
#include <cuda_fp16.h>
#include <stdint.h>
#include <math.h>

#define H   256
#define EMAX 200000

// Scratch (allocation-free rule: static __device__).
__device__ float  g_agg[(size_t)EMAX * H];     // fp32 scatter target (exact atomics)
__device__ __half g_agg_h[(size_t)EMAX * H];   // fp16 quantized copy for GEMM
__device__ __half g_x_h[(size_t)EMAX * H];     // fp16 copy of edge_features
__device__ __half g_wm_h[H * H];
__device__ __half g_wih_h[3 * H * H];
__device__ __half g_whh_h[3 * H * H];
__device__ int g_idx_mode;                     // 1 = int64, 0 = int32

__device__ __forceinline__ void mma_f16(float c[4], const uint32_t a[4],
                                        uint32_t b0, uint32_t b1) {
    asm volatile(
        "mma.sync.aligned.m16n8k16.row.col.f32.f16.f16.f32 "
        "{%0,%1,%2,%3},{%4,%5,%6,%7},{%8,%9},{%0,%1,%2,%3};"
        : "+f"(c[0]), "+f"(c[1]), "+f"(c[2]), "+f"(c[3])
        : "r"(a[0]), "r"(a[1]), "r"(a[2]), "r"(a[3]), "r"(b0), "r"(b1));
}

__device__ __forceinline__ void ldsm_x4(uint32_t& r0, uint32_t& r1, uint32_t& r2, uint32_t& r3,
                                        uint32_t addr) {
    asm volatile("ldmatrix.sync.aligned.m8n8.x4.shared.b16 {%0,%1,%2,%3}, [%4];"
                 : "=r"(r0), "=r"(r1), "=r"(r2), "=r"(r3) : "r"(addr));
}

__device__ __forceinline__ float sigmoidf_(float x) {
    return 1.0f / (1.0f + __expf(-x));
}

__device__ __forceinline__ void cp16(uint32_t dst, const void* src, bool pred) {
    int sz = pred ? 16 : 0;
    asm volatile("cp.async.cg.shared.global [%0], [%1], 16, %2;\n"
                 :: "r"(dst), "l"(src), "r"(sz));
}
__device__ __forceinline__ void cp_commit() {
    asm volatile("cp.async.commit_group;\n");
}
template <int N>
__device__ __forceinline__ void cp_wait() {
    asm volatile("cp.async.wait_group %0;\n" :: "n"(N));
}

// ============================================================================
// Kernel A: detect index dtype.
// ============================================================================
__global__ void detect_idx_kernel(const int* __restrict__ idx32)
{
    __shared__ int ored[256];
    int t = threadIdx.x;
    ored[t] = idx32[2 * t + 1];
    __syncthreads();
    for (int s = 128; s > 0; s >>= 1) {
        if (t < s) ored[t] |= ored[t + s];
        __syncthreads();
    }
    if (t == 0) g_idx_mode = (ored[0] == 0) ? 1 : 0;
}

// ============================================================================
// Kernel 0: zero fp32 agg scratch.
// ============================================================================
__global__ void zero_agg_kernel(int total4)
{
    float4* p = reinterpret_cast<float4*>(g_agg);
    int idx = blockIdx.x * blockDim.x + threadIdx.x;
    int stride = gridDim.x * blockDim.x;
    float4 z = make_float4(0.f, 0.f, 0.f, 0.f);
    for (int i = idx; i < total4; i += stride) p[i] = z;
}

// ============================================================================
// Kernel B: fp32 -> fp16 convert (RN), vectorized 4/thread-iter.
// ============================================================================
__global__ void convert_f2h(const float* __restrict__ src, __half* __restrict__ dst, int n4)
{
    int i = blockIdx.x * blockDim.x + threadIdx.x;
    int stride = gridDim.x * blockDim.x;
    const float4* s4 = (const float4*)src;
    uint2* d4 = (uint2*)dst;
    for (; i < n4; i += stride) {
        float4 v = s4[i];
        __half2 h0 = __floats2half2_rn(v.x, v.y);
        __half2 h1 = __floats2half2_rn(v.z, v.w);
        uint2 o;
        o.x = *reinterpret_cast<uint32_t*>(&h0);
        o.y = *reinterpret_cast<uint32_t*>(&h1);
        d4[i] = o;
    }
}

// ============================================================================
// Kernel 1: message = relu(X16 @ Wm16^T + b); float2 atomics into fp32 agg.
// fp16 m16n8k16 MMA. Tile 128x64, kchunk 32 (2 ksteps), 2-stage, 1 sync/chunk.
// Stage (halves): A[128*40]=5120 @0, B[64*40]=2560 @5120. Stage = 7680 h.
// Row stride 80B ((80/16)=5 odd -> ldmatrix conflict-free).
// ============================================================================
#define MS_STAGE_H 7680

__global__ __launch_bounds__(256)
void msg_scatter_kernel(const void* __restrict__ eidx,
                        const float* __restrict__ bias,
                        int E)
{
    extern __shared__ uint32_t dsm[];
    __shared__ int dsts[128];

    const int tid  = threadIdx.x;
    const int lane = tid & 31;
    const int wid  = tid >> 5;
    const int wm   = wid & 3;
    const int wn   = wid >> 2;
    const int row0 = (int)(blockIdx.x >> 2) * 128;
    const int n0   = (int)(blockIdx.x & 3) * 64;
    const uint32_t sbase = (uint32_t)__cvta_generic_to_shared(dsm);

    const int sub  = lane >> 3;
    const int lrow = lane & 7;
    // byte offsets within a tile: A matrices (m,kL),(m+8,kL),(m,kH),(m+8,kH)
    const int aoffB = ((sub & 1) * 8 + lrow) * 80 + (sub >> 1) * 16;
    // B matrices (n,kL),(n,kH),(n+8,kL),(n+8,kH)
    const int boffB = ((sub >> 1) * 8 + lrow) * 80 + (sub & 1) * 16;

    if (tid < 128) {
        int r = row0 + tid;
        int d = -1;
        if (r < E) {
            d = g_idx_mode ? (int)((const long long*)eidx)[(size_t)E + r]
                           : ((const int*)eidx)[(size_t)E + r];
            if (d < 0 || d >= E) d = -1;
        }
        dsts[tid] = d;
    }

    auto load_stage = [&](int st, int k0) {
        uint32_t sb = sbase + st * (MS_STAGE_H * 2);
        // A: 128 rows x 32k fp16 = 512 16B-chunks (2/thread)
#pragma unroll
        for (int q = 0; q < 2; q++) {
            int f  = tid + q * 256;
            int r  = f >> 2;
            int ch = (f & 3) * 8;
            int gr = row0 + r;
            cp16(sb + (r * 40 + ch) * 2, g_x_h + (size_t)gr * H + k0 + ch, gr < E);
        }
        // B: 64 rows x 32k = 256 chunks (1/thread)
        {
            int r  = tid >> 2;
            int ch = (tid & 3) * 8;
            cp16(sb + (5120 + r * 40 + ch) * 2,
                 g_wm_h + (size_t)(n0 + r) * H + k0 + ch, true);
        }
        cp_commit();
    };

    float acc[2][4][4];
#pragma unroll
    for (int i = 0; i < 2; i++)
#pragma unroll
        for (int j = 0; j < 4; j++)
#pragma unroll
            for (int k = 0; k < 4; k++) acc[i][j][k] = 0.0f;

    load_stage(0, 0);

    for (int kc = 0; kc < 8; kc++) {
        cp_wait<0>();
        __syncthreads();
        if (kc < 7) load_stage((kc + 1) & 1, (kc + 1) * 32);

        const uint32_t Au = sbase + ((kc & 1) * MS_STAGE_H) * 2;
        const uint32_t Bu = Au + 5120 * 2;

#pragma unroll
        for (int ks = 0; ks < 2; ks++) {
            int kb = ks * 32;   // 16 halves = 32 bytes
            uint32_t a[2][4], bb[2][4];
#pragma unroll
            for (int mi = 0; mi < 2; mi++)
                ldsm_x4(a[mi][0], a[mi][1], a[mi][2], a[mi][3],
                        Au + aoffB + (wm * 32 + mi * 16) * 80 + kb);
#pragma unroll
            for (int np = 0; np < 2; np++)
                ldsm_x4(bb[np][0], bb[np][1], bb[np][2], bb[np][3],
                        Bu + boffB + (wn * 32 + np * 16) * 80 + kb);
#pragma unroll
            for (int mi = 0; mi < 2; mi++)
#pragma unroll
                for (int np = 0; np < 2; np++) {
                    mma_f16(acc[mi][2 * np],     a[mi], bb[np][0], bb[np][1]);
                    mma_f16(acc[mi][2 * np + 1], a[mi], bb[np][2], bb[np][3]);
                }
        }
    }

    // ---- epilogue: bias + relu + float2 vector atomics into fp32 agg ----
#pragma unroll
    for (int mi = 0; mi < 2; mi++) {
#pragma unroll
        for (int half = 0; half < 2; half++) {
            int rl = wm * 32 + mi * 16 + (lane >> 2) + half * 8;
            int d  = dsts[rl];
            if (d < 0) continue;
            size_t base = (size_t)d * H;
#pragma unroll
            for (int ni = 0; ni < 4; ni++) {
                int col  = n0 + wn * 32 + ni * 8 + 2 * (lane & 3);
                float v0 = fmaxf(acc[mi][ni][half * 2 + 0] + __ldg(&bias[col]), 0.0f);
                float v1 = fmaxf(acc[mi][ni][half * 2 + 1] + __ldg(&bias[col + 1]), 0.0f);
                atomicAdd(reinterpret_cast<float2*>(&g_agg[base + col]),
                          make_float2(v0, v1));
            }
        }
    }
}

// ============================================================================
// Kernel 2: GRU fused GEMMs, fp16 operands. Round-11 structure (384 thr,
// 2/SM, warp=(row-half, gate), kchunk 32, 1 sync/chunk, y-fast grid).
// Stage (halves): Aagg[64*40]=2560 @0, Ax @2560, B[192*40]=7680 @5120.
// Stage = 12800 h = 25.6KB; 2 stages = 51.2KB; gbuf 48KB aliases ring.
// ============================================================================
#define GK_STAGE_H 12800

__global__ __launch_bounds__(384, 2)
void gru_kernel(const float* __restrict__ X,
                const float* __restrict__ bih,
                const float* __restrict__ bhh,
                float* __restrict__ out,
                int E)
{
    extern __shared__ uint32_t dsm[];
    float* gbuf = reinterpret_cast<float*>(dsm);

    const int tid  = threadIdx.x;
    const int lane = tid & 31;
    const int wid  = tid >> 5;
    const int wm   = wid & 1;
    const int g    = wid >> 1;
    const int row0 = (int)(blockIdx.x >> 3) * 64;
    const int n0   = (int)(blockIdx.x & 7) * 32;
    const uint32_t sbase = (uint32_t)__cvta_generic_to_shared(dsm);

    const int sub  = lane >> 3;
    const int lrow = lane & 7;
    const int aoffB = ((sub & 1) * 8 + lrow) * 80 + (sub >> 1) * 16;
    const int boffB = ((sub >> 1) * 8 + lrow) * 80 + (sub & 1) * 16;

    auto load_stage = [&](int st, int k0) {
        uint32_t sb = sbase + st * (GK_STAGE_H * 2);
        // A: agg16(64x32) + X16(64x32) = 512 chunks
        for (int f = tid; f < 512; f += 384) {
            int which = f >> 8;
            int rem   = f & 255;
            int r     = rem >> 2;
            int ch    = (rem & 3) * 8;
            int gr    = row0 + r;
            const __half* src = which ? (g_x_h + (size_t)gr * H)
                                      : (g_agg_h + (size_t)gr * H);
            cp16(sb + ((which ? 2560 : 0) + r * 40 + ch) * 2, src + k0 + ch, gr < E);
        }
        // B: 6 gate tiles 32x32 = 768 chunks (2/thread)
#pragma unroll
        for (int q = 0; q < 2; q++) {
            int f    = tid + q * 384;
            int g2   = f >> 7;
            int rem  = f & 127;
            int r    = rem >> 2;
            int ch   = (rem & 3) * 8;
            int gate = (g2 < 3) ? g2 : (g2 - 3);
            const __half* Wsrc = (g2 < 3) ? g_wih_h : g_whh_h;
            cp16(sb + (5120 + (g2 * 32 + r) * 40 + ch) * 2,
                 Wsrc + (size_t)(gate * H + n0 + r) * H + k0 + ch, true);
        }
        cp_commit();
    };

    float acc[2][4][4];
#pragma unroll
    for (int i = 0; i < 2; i++)
#pragma unroll
        for (int j = 0; j < 4; j++)
#pragma unroll
            for (int k = 0; k < 4; k++) acc[i][j][k] = 0.0f;

    load_stage(0, 0);

    for (int kc = 0; kc < 8; kc++) {
        cp_wait<0>();
        __syncthreads();
        if (kc < 7) load_stage((kc + 1) & 1, (kc + 1) * 32);

        const uint32_t Su = sbase + ((kc & 1) * GK_STAGE_H) * 2;
        const uint32_t Au = Su + ((g < 3) ? 0 : 2560) * 2;
        const uint32_t Bu = Su + 5120 * 2;

#pragma unroll
        for (int ks = 0; ks < 2; ks++) {
            int kb = ks * 32;
            uint32_t a[2][4], bb[2][4];
#pragma unroll
            for (int mi = 0; mi < 2; mi++)
                ldsm_x4(a[mi][0], a[mi][1], a[mi][2], a[mi][3],
                        Au + aoffB + (wm * 32 + mi * 16) * 80 + kb);
#pragma unroll
            for (int np = 0; np < 2; np++)
                ldsm_x4(bb[np][0], bb[np][1], bb[np][2], bb[np][3],
                        Bu + boffB + (g * 32 + np * 16) * 80 + kb);
#pragma unroll
            for (int mi = 0; mi < 2; mi++)
#pragma unroll
                for (int np = 0; np < 2; np++) {
                    mma_f16(acc[mi][2 * np],     a[mi], bb[np][0], bb[np][1]);
                    mma_f16(acc[mi][2 * np + 1], a[mi], bb[np][2], bb[np][3]);
                }
        }
    }

    __syncthreads();   // all warps done reading the ring before gbuf aliasing

    // ---- dump accumulators: gbuf[r][g*32 + c], row stride 192, float2 ----
#pragma unroll
    for (int mi = 0; mi < 2; mi++) {
        int r = wm * 32 + mi * 16 + (lane >> 2);
#pragma unroll
        for (int ni = 0; ni < 4; ni++) {
            int c = g * 32 + ni * 8 + 2 * (lane & 3);
            *reinterpret_cast<float2*>(&gbuf[r * 192 + c]) =
                make_float2(acc[mi][ni][0], acc[mi][ni][1]);
            *reinterpret_cast<float2*>(&gbuf[(r + 8) * 192 + c]) =
                make_float2(acc[mi][ni][2], acc[mi][ni][3]);
        }
    }
    __syncthreads();

    // ---- GRU gate math + output ----
    for (int idx = tid; idx < 64 * 32; idx += 384) {
        int r  = idx >> 5;
        int c  = idx & 31;
        int gr = row0 + r;
        if (gr >= E) continue;
        int gc = n0 + c;
        const float* gr_ = &gbuf[r * 192];
        float i_r = gr_[c]       + __ldg(&bih[gc]);
        float i_z = gr_[32 + c]  + __ldg(&bih[H + gc]);
        float i_n = gr_[64 + c]  + __ldg(&bih[2 * H + gc]);
        float h_r = gr_[96 + c]  + __ldg(&bhh[gc]);
        float h_z = gr_[128 + c] + __ldg(&bhh[H + gc]);
        float h_n = gr_[160 + c] + __ldg(&bhh[2 * H + gc]);

        float rg = sigmoidf_(i_r + h_r);
        float z  = sigmoidf_(i_z + h_z);
        float n  = tanhf(i_n + rg * h_n);
        float hp = __ldg(&X[(size_t)gr * H + gc]);
        out[(size_t)gr * H + gc] = (1.0f - z) * n + z * hp;
    }
}

// ============================================================================
extern "C" void kernel_launch(void* const* d_in, const int* in_sizes, int n_in,
                              void* d_out, int out_size)
{
    const float* X   = (const float*)d_in[0];
    const void*  ei  = d_in[1];
    const float* Wm  = (const float*)d_in[2];
    const float* bm  = (const float*)d_in[3];
    const float* Wih = (const float*)d_in[4];
    const float* Whh = (const float*)d_in[5];
    const float* bih = (const float*)d_in[6];
    const float* bhh = (const float*)d_in[7];
    float*       out = (float*)d_out;

    int E = in_sizes[0] / H;

    cudaFuncSetAttribute(msg_scatter_kernel,
                         cudaFuncAttributeMaxDynamicSharedMemorySize, 2 * MS_STAGE_H * 2);
    cudaFuncSetAttribute(gru_kernel,
                         cudaFuncAttributeMaxDynamicSharedMemorySize, 2 * GK_STAGE_H * 2);

    __half *xh, *wmh, *wihh, *whhh, *aggh;
    float* aggf;
    cudaGetSymbolAddress((void**)&xh,   g_x_h);
    cudaGetSymbolAddress((void**)&wmh,  g_wm_h);
    cudaGetSymbolAddress((void**)&wihh, g_wih_h);
    cudaGetSymbolAddress((void**)&whhh, g_whh_h);
    cudaGetSymbolAddress((void**)&aggh, g_agg_h);
    cudaGetSymbolAddress((void**)&aggf, g_agg);

    detect_idx_kernel<<<1, 256>>>((const int*)ei);
    zero_agg_kernel<<<4096, 256>>>((E * H) / 4);

    // one-time fp32 -> fp16 conversions
    convert_f2h<<<4096, 256>>>(X,   xh,   (E * H) / 4);
    convert_f2h<<<64,   256>>>(Wm,  wmh,  (H * H) / 4);
    convert_f2h<<<192,  256>>>(Wih, wihh, (3 * H * H) / 4);
    convert_f2h<<<192,  256>>>(Whh, whhh, (3 * H * H) / 4);

    int mrows = (E + 127) / 128;
    msg_scatter_kernel<<<mrows * 4, 256, 2 * MS_STAGE_H * 2>>>(ei, bm, E);

    // quantize agg once (RN), same mantissa budget as tf32 truncation
    convert_f2h<<<4096, 256>>>(aggf, aggh, (E * H) / 4);

    int grows = (E + 63) / 64;
    gru_kernel<<<grows * 8, 384, 2 * GK_STAGE_H * 2>>>(X, bih, bhh, out, E);
}

// round 13
// speedup vs baseline: 1.3601x; 1.0931x over previous
#include <cuda_runtime.h>
#include <cuda_fp16.h>
#include <stdint.h>
#include <math.h>

#define H   256
#define EMAX 200000

// Scratch (allocation-free rule: static __device__).
__device__ float  g_agg[(size_t)EMAX * H];     // fp32 scatter target (exact atomics)
__device__ __half g_agg_h[(size_t)EMAX * H];   // fp16 quantized copy for GEMM
__device__ __half g_x_h[(size_t)EMAX * H];     // fp16 copy of edge_features
__device__ __half g_wm_h[H * H];
__device__ __half g_wih_h[3 * H * H];
__device__ __half g_whh_h[3 * H * H];
__device__ int g_idx_mode;                     // 1 = int64, 0 = int32

__device__ __forceinline__ void mma_f16(float c[4], const uint32_t a[4],
                                        uint32_t b0, uint32_t b1) {
    asm volatile(
        "mma.sync.aligned.m16n8k16.row.col.f32.f16.f16.f32 "
        "{%0,%1,%2,%3},{%4,%5,%6,%7},{%8,%9},{%0,%1,%2,%3};"
        : "+f"(c[0]), "+f"(c[1]), "+f"(c[2]), "+f"(c[3])
        : "r"(a[0]), "r"(a[1]), "r"(a[2]), "r"(a[3]), "r"(b0), "r"(b1));
}

__device__ __forceinline__ void ldsm_x4(uint32_t& r0, uint32_t& r1, uint32_t& r2, uint32_t& r3,
                                        uint32_t addr) {
    asm volatile("ldmatrix.sync.aligned.m8n8.x4.shared.b16 {%0,%1,%2,%3}, [%4];"
                 : "=r"(r0), "=r"(r1), "=r"(r2), "=r"(r3) : "r"(addr));
}

__device__ __forceinline__ float sigmoidf_(float x) {
    return 1.0f / (1.0f + __expf(-x));
}

__device__ __forceinline__ void cp16(uint32_t dst, const void* src, bool pred) {
    int sz = pred ? 16 : 0;
    asm volatile("cp.async.cg.shared.global [%0], [%1], 16, %2;\n"
                 :: "r"(dst), "l"(src), "r"(sz));
}
__device__ __forceinline__ void cp_commit() {
    asm volatile("cp.async.commit_group;\n");
}
template <int N>
__device__ __forceinline__ void cp_wait() {
    asm volatile("cp.async.wait_group %0;\n" :: "n"(N));
}

// ============================================================================
// Kernel A (launch 1): detect index dtype.
// ============================================================================
__global__ void detect_idx_kernel(const int* __restrict__ idx32)
{
    __shared__ int ored[256];
    int t = threadIdx.x;
    ored[t] = idx32[2 * t + 1];
    __syncthreads();
    for (int s = 128; s > 0; s >>= 1) {
        if (t < s) ored[t] |= ored[t + s];
        __syncthreads();
    }
    if (t == 0) g_idx_mode = (ored[0] == 0) ? 1 : 0;
}

// ============================================================================
// Kernel 0 (launch 2): zero fp32 agg scratch.
// ============================================================================
__global__ void zero_agg_kernel(int total4)
{
    float4* p = reinterpret_cast<float4*>(g_agg);
    int idx = blockIdx.x * blockDim.x + threadIdx.x;
    int stride = gridDim.x * blockDim.x;
    float4 z = make_float4(0.f, 0.f, 0.f, 0.f);
    for (int i = idx; i < total4; i += stride) p[i] = z;
}

// ============================================================================
// fp32 -> fp16 segment converter (device helper)
// ============================================================================
__device__ __forceinline__ void conv_seg(const float* __restrict__ src,
                                         __half* __restrict__ dst, int n4,
                                         int idx, int stride)
{
    const float4* s4 = (const float4*)src;
    uint2* d4 = (uint2*)dst;
    for (int i = idx; i < n4; i += stride) {
        float4 v = s4[i];
        __half2 h0 = __floats2half2_rn(v.x, v.y);
        __half2 h1 = __floats2half2_rn(v.z, v.w);
        uint2 o;
        o.x = *reinterpret_cast<uint32_t*>(&h0);
        o.y = *reinterpret_cast<uint32_t*>(&h1);
        d4[i] = o;
    }
}

// Kernel B (launch 3): convert X + all three weight matrices in ONE launch.
__global__ void convert_inputs_kernel(const float* __restrict__ X,
                                      const float* __restrict__ Wm,
                                      const float* __restrict__ Wih,
                                      const float* __restrict__ Whh,
                                      int exh4)
{
    int idx = blockIdx.x * blockDim.x + threadIdx.x;
    int stride = gridDim.x * blockDim.x;
    conv_seg(X,   g_x_h,   exh4,            idx, stride);
    conv_seg(Wm,  g_wm_h,  (H * H) / 4,     idx, stride);
    conv_seg(Wih, g_wih_h, (3 * H * H) / 4, idx, stride);
    conv_seg(Whh, g_whh_h, (3 * H * H) / 4, idx, stride);
}

// Kernel C (launch 5): quantize fp32 agg -> fp16.
__global__ void convert_agg_kernel(int n4)
{
    int idx = blockIdx.x * blockDim.x + threadIdx.x;
    int stride = gridDim.x * blockDim.x;
    conv_seg(g_agg, g_agg_h, n4, idx, stride);
}

// ============================================================================
// Kernel 1 (launch 4): message = relu(X16 @ Wm16^T + b) + float2 atomics.
// fp16 m16n8k16. Tile 128x64, kchunk 64 (4 ksteps), 2-stage, 1 sync/chunk.
// Stage (halves): A[128*72]=9216 @0, B[64*72]=4608 @9216. Stage = 13824 h.
// Row stride 144B -> ldmatrix rows hit distinct banks (r*144 mod 128 distinct).
// ============================================================================
#define MS_STAGE_H 13824

__global__ __launch_bounds__(256)
void msg_scatter_kernel(const void* __restrict__ eidx,
                        const float* __restrict__ bias,
                        int E)
{
    extern __shared__ uint32_t dsm[];
    __shared__ int dsts[128];

    const int tid  = threadIdx.x;
    const int lane = tid & 31;
    const int wid  = tid >> 5;
    const int wm   = wid & 3;
    const int wn   = wid >> 2;
    const int row0 = (int)(blockIdx.x >> 2) * 128;
    const int n0   = (int)(blockIdx.x & 3) * 64;
    const uint32_t sbase = (uint32_t)__cvta_generic_to_shared(dsm);

    const int sub  = lane >> 3;
    const int lrow = lane & 7;
    const int aoffB = ((sub & 1) * 8 + lrow) * 144 + (sub >> 1) * 16;
    const int boffB = ((sub >> 1) * 8 + lrow) * 144 + (sub & 1) * 16;

    if (tid < 128) {
        int r = row0 + tid;
        int d = -1;
        if (r < E) {
            d = g_idx_mode ? (int)((const long long*)eidx)[(size_t)E + r]
                           : ((const int*)eidx)[(size_t)E + r];
            if (d < 0 || d >= E) d = -1;
        }
        dsts[tid] = d;
    }

    auto load_stage = [&](int st, int k0) {
        uint32_t sb = sbase + st * (MS_STAGE_H * 2);
        // A: 128 rows x 64 halves = 1024 16B-chunks (4/thread)
#pragma unroll
        for (int q = 0; q < 4; q++) {
            int f  = tid + q * 256;
            int r  = f >> 3;
            int ch = (f & 7) * 8;
            int gr = row0 + r;
            cp16(sb + (r * 72 + ch) * 2, g_x_h + (size_t)gr * H + k0 + ch, gr < E);
        }
        // B: 64 rows x 64 halves = 512 chunks (2/thread)
#pragma unroll
        for (int q = 0; q < 2; q++) {
            int f  = tid + q * 256;
            int r  = f >> 3;
            int ch = (f & 7) * 8;
            cp16(sb + (9216 + r * 72 + ch) * 2,
                 g_wm_h + (size_t)(n0 + r) * H + k0 + ch, true);
        }
        cp_commit();
    };

    float acc[2][4][4];
#pragma unroll
    for (int i = 0; i < 2; i++)
#pragma unroll
        for (int j = 0; j < 4; j++)
#pragma unroll
            for (int k = 0; k < 4; k++) acc[i][j][k] = 0.0f;

    load_stage(0, 0);

    for (int kc = 0; kc < 4; kc++) {
        cp_wait<0>();
        __syncthreads();
        if (kc < 3) load_stage((kc + 1) & 1, (kc + 1) * 64);

        const uint32_t Au = sbase + ((kc & 1) * MS_STAGE_H) * 2;
        const uint32_t Bu = Au + 9216 * 2;

#pragma unroll
        for (int ks = 0; ks < 4; ks++) {
            int kb = ks * 32;   // 16 halves = 32 bytes
            uint32_t a[2][4], bb[2][4];
#pragma unroll
            for (int mi = 0; mi < 2; mi++)
                ldsm_x4(a[mi][0], a[mi][1], a[mi][2], a[mi][3],
                        Au + aoffB + (wm * 32 + mi * 16) * 144 + kb);
#pragma unroll
            for (int np = 0; np < 2; np++)
                ldsm_x4(bb[np][0], bb[np][1], bb[np][2], bb[np][3],
                        Bu + boffB + (wn * 32 + np * 16) * 144 + kb);
#pragma unroll
            for (int mi = 0; mi < 2; mi++)
#pragma unroll
                for (int np = 0; np < 2; np++) {
                    mma_f16(acc[mi][2 * np],     a[mi], bb[np][0], bb[np][1]);
                    mma_f16(acc[mi][2 * np + 1], a[mi], bb[np][2], bb[np][3]);
                }
        }
    }

    // ---- epilogue: bias + relu + float2 vector atomics into fp32 agg ----
#pragma unroll
    for (int mi = 0; mi < 2; mi++) {
#pragma unroll
        for (int half = 0; half < 2; half++) {
            int rl = wm * 32 + mi * 16 + (lane >> 2) + half * 8;
            int d  = dsts[rl];
            if (d < 0) continue;
            size_t base = (size_t)d * H;
#pragma unroll
            for (int ni = 0; ni < 4; ni++) {
                int col  = n0 + wn * 32 + ni * 8 + 2 * (lane & 3);
                float v0 = fmaxf(acc[mi][ni][half * 2 + 0] + __ldg(&bias[col]), 0.0f);
                float v1 = fmaxf(acc[mi][ni][half * 2 + 1] + __ldg(&bias[col + 1]), 0.0f);
                atomicAdd(reinterpret_cast<float2*>(&g_agg[base + col]),
                          make_float2(v0, v1));
            }
        }
    }
}

// ============================================================================
// Kernel 2 (launch 6): GRU fused GEMMs, fp16, kchunk 64, 1 sync/chunk.
// 384 thr, 2/SM, warp=(row-half, gate), y-fast grid.
// Stage (halves): Aagg[64*72]=4608 @0, Ax @4608, B[192*72]=13824 @9216.
// Stage = 23040 h = 46KB; 2 stages = 92KB; gbuf 48KB aliases ring.
// ============================================================================
#define GK_STAGE_H 23040

__global__ __launch_bounds__(384, 2)
void gru_kernel(const float* __restrict__ X,
                const float* __restrict__ bih,
                const float* __restrict__ bhh,
                float* __restrict__ out,
                int E)
{
    extern __shared__ uint32_t dsm[];
    float* gbuf = reinterpret_cast<float*>(dsm);

    const int tid  = threadIdx.x;
    const int lane = tid & 31;
    const int wid  = tid >> 5;
    const int wm   = wid & 1;
    const int g    = wid >> 1;
    const int row0 = (int)(blockIdx.x >> 3) * 64;
    const int n0   = (int)(blockIdx.x & 7) * 32;
    const uint32_t sbase = (uint32_t)__cvta_generic_to_shared(dsm);

    const int sub  = lane >> 3;
    const int lrow = lane & 7;
    const int aoffB = ((sub & 1) * 8 + lrow) * 144 + (sub >> 1) * 16;
    const int boffB = ((sub >> 1) * 8 + lrow) * 144 + (sub & 1) * 16;

    auto load_stage = [&](int st, int k0) {
        uint32_t sb = sbase + st * (GK_STAGE_H * 2);
        // A: agg16(64x64) + X16(64x64) = 1024 chunks
        for (int f = tid; f < 1024; f += 384) {
            int which = f >> 9;
            int rem   = f & 511;
            int r     = rem >> 3;
            int ch    = (rem & 7) * 8;
            int gr    = row0 + r;
            const __half* src = which ? (g_x_h + (size_t)gr * H)
                                      : (g_agg_h + (size_t)gr * H);
            cp16(sb + ((which ? 4608 : 0) + r * 72 + ch) * 2, src + k0 + ch, gr < E);
        }
        // B: 6 gate tiles 32x64 = 1536 chunks (4/thread)
#pragma unroll
        for (int q = 0; q < 4; q++) {
            int f    = tid + q * 384;
            int g2   = f >> 8;
            int rem  = f & 255;
            int r    = rem >> 3;
            int ch   = (rem & 7) * 8;
            int gate = (g2 < 3) ? g2 : (g2 - 3);
            const __half* Wsrc = (g2 < 3) ? g_wih_h : g_whh_h;
            cp16(sb + (9216 + (g2 * 32 + r) * 72 + ch) * 2,
                 Wsrc + (size_t)(gate * H + n0 + r) * H + k0 + ch, true);
        }
        cp_commit();
    };

    float acc[2][4][4];
#pragma unroll
    for (int i = 0; i < 2; i++)
#pragma unroll
        for (int j = 0; j < 4; j++)
#pragma unroll
            for (int k = 0; k < 4; k++) acc[i][j][k] = 0.0f;

    load_stage(0, 0);

    for (int kc = 0; kc < 4; kc++) {
        cp_wait<0>();
        __syncthreads();
        if (kc < 3) load_stage((kc + 1) & 1, (kc + 1) * 64);

        const uint32_t Su = sbase + ((kc & 1) * GK_STAGE_H) * 2;
        const uint32_t Au = Su + ((g < 3) ? 0 : 4608) * 2;
        const uint32_t Bu = Su + 9216 * 2;

#pragma unroll
        for (int ks = 0; ks < 4; ks++) {
            int kb = ks * 32;
            uint32_t a[2][4], bb[2][4];
#pragma unroll
            for (int mi = 0; mi < 2; mi++)
                ldsm_x4(a[mi][0], a[mi][1], a[mi][2], a[mi][3],
                        Au + aoffB + (wm * 32 + mi * 16) * 144 + kb);
#pragma unroll
            for (int np = 0; np < 2; np++)
                ldsm_x4(bb[np][0], bb[np][1], bb[np][2], bb[np][3],
                        Bu + boffB + (g * 32 + np * 16) * 144 + kb);
#pragma unroll
            for (int mi = 0; mi < 2; mi++)
#pragma unroll
                for (int np = 0; np < 2; np++) {
                    mma_f16(acc[mi][2 * np],     a[mi], bb[np][0], bb[np][1]);
                    mma_f16(acc[mi][2 * np + 1], a[mi], bb[np][2], bb[np][3]);
                }
        }
    }

    __syncthreads();   // all warps done reading the ring before gbuf aliasing

    // ---- dump accumulators: gbuf[r][g*32 + c], row stride 192, float2 ----
#pragma unroll
    for (int mi = 0; mi < 2; mi++) {
        int r = wm * 32 + mi * 16 + (lane >> 2);
#pragma unroll
        for (int ni = 0; ni < 4; ni++) {
            int c = g * 32 + ni * 8 + 2 * (lane & 3);
            *reinterpret_cast<float2*>(&gbuf[r * 192 + c]) =
                make_float2(acc[mi][ni][0], acc[mi][ni][1]);
            *reinterpret_cast<float2*>(&gbuf[(r + 8) * 192 + c]) =
                make_float2(acc[mi][ni][2], acc[mi][ni][3]);
        }
    }
    __syncthreads();

    // ---- GRU gate math + output ----
    for (int idx = tid; idx < 64 * 32; idx += 384) {
        int r  = idx >> 5;
        int c  = idx & 31;
        int gr = row0 + r;
        if (gr >= E) continue;
        int gc = n0 + c;
        const float* gr_ = &gbuf[r * 192];
        float i_r = gr_[c]       + __ldg(&bih[gc]);
        float i_z = gr_[32 + c]  + __ldg(&bih[H + gc]);
        float i_n = gr_[64 + c]  + __ldg(&bih[2 * H + gc]);
        float h_r = gr_[96 + c]  + __ldg(&bhh[gc]);
        float h_z = gr_[128 + c] + __ldg(&bhh[H + gc]);
        float h_n = gr_[160 + c] + __ldg(&bhh[2 * H + gc]);

        float rg = sigmoidf_(i_r + h_r);
        float z  = sigmoidf_(i_z + h_z);
        float n  = tanhf(i_n + rg * h_n);
        float hp = __ldg(&X[(size_t)gr * H + gc]);
        out[(size_t)gr * H + gc] = (1.0f - z) * n + z * hp;
    }
}

// ============================================================================
extern "C" void kernel_launch(void* const* d_in, const int* in_sizes, int n_in,
                              void* d_out, int out_size)
{
    const float* X   = (const float*)d_in[0];
    const void*  ei  = d_in[1];
    const float* Wm  = (const float*)d_in[2];
    const float* bm  = (const float*)d_in[3];
    const float* Wih = (const float*)d_in[4];
    const float* Whh = (const float*)d_in[5];
    const float* bih = (const float*)d_in[6];
    const float* bhh = (const float*)d_in[7];
    float*       out = (float*)d_out;

    int E = in_sizes[0] / H;

    cudaFuncSetAttribute(msg_scatter_kernel,
                         cudaFuncAttributeMaxDynamicSharedMemorySize, 2 * MS_STAGE_H * 2);
    cudaFuncSetAttribute(gru_kernel,
                         cudaFuncAttributeMaxDynamicSharedMemorySize, 2 * GK_STAGE_H * 2);

    // launch order matters for ncu -s 5 -c 1: gru is launch #6.
    detect_idx_kernel<<<1, 256>>>((const int*)ei);                        // 1
    zero_agg_kernel<<<4096, 256>>>((E * H) / 4);                          // 2
    convert_inputs_kernel<<<4096, 256>>>(X, Wm, Wih, Whh, (E * H) / 4);   // 3

    int mrows = (E + 127) / 128;
    msg_scatter_kernel<<<mrows * 4, 256, 2 * MS_STAGE_H * 2>>>(ei, bm, E); // 4

    convert_agg_kernel<<<4096, 256>>>((E * H) / 4);                        // 5

    int grows = (E + 63) / 64;
    gru_kernel<<<grows * 8, 384, 2 * GK_STAGE_H * 2>>>(X, bih, bhh, out, E); // 6
}

// round 14
// speedup vs baseline: 1.4075x; 1.0348x over previous
#include <cuda_runtime.h>
#include <cuda_fp16.h>
#include <stdint.h>
#include <math.h>

#define H   256
#define EMAX 200000

// Scratch (allocation-free rule: static __device__).
__device__ __half g_agg_h[(size_t)EMAX * H];   // fp16 scatter target (RED.F16x2)
__device__ __half g_x_h[(size_t)EMAX * H];     // fp16 copy of edge_features
__device__ __half g_wm_h[H * H];
__device__ __half g_wih_h[3 * H * H];
__device__ __half g_whh_h[3 * H * H];
__device__ int g_idx_mode;                     // 1 = int64, 0 = int32

__device__ __forceinline__ void mma_f16(float c[4], const uint32_t a[4],
                                        uint32_t b0, uint32_t b1) {
    asm volatile(
        "mma.sync.aligned.m16n8k16.row.col.f32.f16.f16.f32 "
        "{%0,%1,%2,%3},{%4,%5,%6,%7},{%8,%9},{%0,%1,%2,%3};"
        : "+f"(c[0]), "+f"(c[1]), "+f"(c[2]), "+f"(c[3])
        : "r"(a[0]), "r"(a[1]), "r"(a[2]), "r"(a[3]), "r"(b0), "r"(b1));
}

__device__ __forceinline__ void ldsm_x4(uint32_t& r0, uint32_t& r1, uint32_t& r2, uint32_t& r3,
                                        uint32_t addr) {
    asm volatile("ldmatrix.sync.aligned.m8n8.x4.shared.b16 {%0,%1,%2,%3}, [%4];"
                 : "=r"(r0), "=r"(r1), "=r"(r2), "=r"(r3) : "r"(addr));
}

__device__ __forceinline__ float sigmoidf_(float x) {
    return 1.0f / (1.0f + __expf(-x));
}

__device__ __forceinline__ void cp16(uint32_t dst, const void* src, bool pred) {
    int sz = pred ? 16 : 0;
    asm volatile("cp.async.cg.shared.global [%0], [%1], 16, %2;\n"
                 :: "r"(dst), "l"(src), "r"(sz));
}
__device__ __forceinline__ void cp_commit() {
    asm volatile("cp.async.commit_group;\n");
}
template <int N>
__device__ __forceinline__ void cp_wait() {
    asm volatile("cp.async.wait_group %0;\n" :: "n"(N));
}

// ============================================================================
// Kernel A (launch 1): detect index dtype.
// ============================================================================
__global__ void detect_idx_kernel(const int* __restrict__ idx32)
{
    __shared__ int ored[256];
    int t = threadIdx.x;
    ored[t] = idx32[2 * t + 1];
    __syncthreads();
    for (int s = 128; s > 0; s >>= 1) {
        if (t < s) ored[t] |= ored[t + s];
        __syncthreads();
    }
    if (t == 0) g_idx_mode = (ored[0] == 0) ? 1 : 0;
}

// ============================================================================
// Kernel 0 (launch 2): zero fp16 agg scratch (uint4 = 8 halves per store).
// ============================================================================
__global__ void zero_agg_kernel(int total8)
{
    uint4* p = reinterpret_cast<uint4*>(g_agg_h);
    int idx = blockIdx.x * blockDim.x + threadIdx.x;
    int stride = gridDim.x * blockDim.x;
    uint4 z = make_uint4(0, 0, 0, 0);
    for (int i = idx; i < total8; i += stride) p[i] = z;
}

// ============================================================================
// fp32 -> fp16 segment converter (device helper)
// ============================================================================
__device__ __forceinline__ void conv_seg(const float* __restrict__ src,
                                         __half* __restrict__ dst, int n4,
                                         int idx, int stride)
{
    const float4* s4 = (const float4*)src;
    uint2* d4 = (uint2*)dst;
    for (int i = idx; i < n4; i += stride) {
        float4 v = s4[i];
        __half2 h0 = __floats2half2_rn(v.x, v.y);
        __half2 h1 = __floats2half2_rn(v.z, v.w);
        uint2 o;
        o.x = *reinterpret_cast<uint32_t*>(&h0);
        o.y = *reinterpret_cast<uint32_t*>(&h1);
        d4[i] = o;
    }
}

// Kernel B (launch 3): convert X + all three weight matrices in ONE launch.
__global__ void convert_inputs_kernel(const float* __restrict__ X,
                                      const float* __restrict__ Wm,
                                      const float* __restrict__ Wih,
                                      const float* __restrict__ Whh,
                                      int exh4)
{
    int idx = blockIdx.x * blockDim.x + threadIdx.x;
    int stride = gridDim.x * blockDim.x;
    conv_seg(X,   g_x_h,   exh4,            idx, stride);
    conv_seg(Wm,  g_wm_h,  (H * H) / 4,     idx, stride);
    conv_seg(Wih, g_wih_h, (3 * H * H) / 4, idx, stride);
    conv_seg(Whh, g_whh_h, (3 * H * H) / 4, idx, stride);
}

// ============================================================================
// Kernel 1 (launch 4): message = relu(X16 @ Wm16^T + b); RED.F16x2 scatter.
// fp16 m16n8k16. Tile 128x64, kchunk 64 (4 ksteps), 2-stage, 1 sync/chunk.
// Stage (halves): A[128*72]=9216 @0, B[64*72]=4608 @9216. Stage = 13824 h.
// ============================================================================
#define MS_STAGE_H 13824

__global__ __launch_bounds__(256)
void msg_scatter_kernel(const void* __restrict__ eidx,
                        const float* __restrict__ bias,
                        int E)
{
    extern __shared__ uint32_t dsm[];
    __shared__ int dsts[128];

    const int tid  = threadIdx.x;
    const int lane = tid & 31;
    const int wid  = tid >> 5;
    const int wm   = wid & 3;
    const int wn   = wid >> 2;
    const int row0 = (int)(blockIdx.x >> 2) * 128;
    const int n0   = (int)(blockIdx.x & 3) * 64;
    const uint32_t sbase = (uint32_t)__cvta_generic_to_shared(dsm);

    const int sub  = lane >> 3;
    const int lrow = lane & 7;
    const int aoffB = ((sub & 1) * 8 + lrow) * 144 + (sub >> 1) * 16;
    const int boffB = ((sub >> 1) * 8 + lrow) * 144 + (sub & 1) * 16;

    if (tid < 128) {
        int r = row0 + tid;
        int d = -1;
        if (r < E) {
            d = g_idx_mode ? (int)((const long long*)eidx)[(size_t)E + r]
                           : ((const int*)eidx)[(size_t)E + r];
            if (d < 0 || d >= E) d = -1;
        }
        dsts[tid] = d;
    }

    auto load_stage = [&](int st, int k0) {
        uint32_t sb = sbase + st * (MS_STAGE_H * 2);
#pragma unroll
        for (int q = 0; q < 4; q++) {
            int f  = tid + q * 256;
            int r  = f >> 3;
            int ch = (f & 7) * 8;
            int gr = row0 + r;
            cp16(sb + (r * 72 + ch) * 2, g_x_h + (size_t)gr * H + k0 + ch, gr < E);
        }
#pragma unroll
        for (int q = 0; q < 2; q++) {
            int f  = tid + q * 256;
            int r  = f >> 3;
            int ch = (f & 7) * 8;
            cp16(sb + (9216 + r * 72 + ch) * 2,
                 g_wm_h + (size_t)(n0 + r) * H + k0 + ch, true);
        }
        cp_commit();
    };

    float acc[2][4][4];
#pragma unroll
    for (int i = 0; i < 2; i++)
#pragma unroll
        for (int j = 0; j < 4; j++)
#pragma unroll
            for (int k = 0; k < 4; k++) acc[i][j][k] = 0.0f;

    load_stage(0, 0);

    for (int kc = 0; kc < 4; kc++) {
        cp_wait<0>();
        __syncthreads();
        if (kc < 3) load_stage((kc + 1) & 1, (kc + 1) * 64);

        const uint32_t Au = sbase + ((kc & 1) * MS_STAGE_H) * 2;
        const uint32_t Bu = Au + 9216 * 2;

#pragma unroll
        for (int ks = 0; ks < 4; ks++) {
            int kb = ks * 32;
            uint32_t a[2][4], bb[2][4];
#pragma unroll
            for (int mi = 0; mi < 2; mi++)
                ldsm_x4(a[mi][0], a[mi][1], a[mi][2], a[mi][3],
                        Au + aoffB + (wm * 32 + mi * 16) * 144 + kb);
#pragma unroll
            for (int np = 0; np < 2; np++)
                ldsm_x4(bb[np][0], bb[np][1], bb[np][2], bb[np][3],
                        Bu + boffB + (wn * 32 + np * 16) * 144 + kb);
#pragma unroll
            for (int mi = 0; mi < 2; mi++)
#pragma unroll
                for (int np = 0; np < 2; np++) {
                    mma_f16(acc[mi][2 * np],     a[mi], bb[np][0], bb[np][1]);
                    mma_f16(acc[mi][2 * np + 1], a[mi], bb[np][2], bb[np][3]);
                }
        }
    }

    // ---- epilogue: bias + relu + fp16x2 vector atomics (RED.ADD.F16x2) ----
#pragma unroll
    for (int mi = 0; mi < 2; mi++) {
#pragma unroll
        for (int half = 0; half < 2; half++) {
            int rl = wm * 32 + mi * 16 + (lane >> 2) + half * 8;
            int d  = dsts[rl];
            if (d < 0) continue;
            size_t base = (size_t)d * H;
#pragma unroll
            for (int ni = 0; ni < 4; ni++) {
                int col  = n0 + wn * 32 + ni * 8 + 2 * (lane & 3);   // even -> 4B aligned
                float v0 = fmaxf(acc[mi][ni][half * 2 + 0] + __ldg(&bias[col]), 0.0f);
                float v1 = fmaxf(acc[mi][ni][half * 2 + 1] + __ldg(&bias[col + 1]), 0.0f);
                __half2 hv = __floats2half2_rn(v0, v1);
                atomicAdd(reinterpret_cast<__half2*>(&g_agg_h[base + col]), hv);
            }
        }
    }
}

// ============================================================================
// Kernel 2 (launch 5): GRU fused GEMMs, fp16, kchunk 64, 1 sync/chunk.
// (byte-identical mainloop to round 13)
// ============================================================================
#define GK_STAGE_H 23040

__global__ __launch_bounds__(384, 2)
void gru_kernel(const float* __restrict__ X,
                const float* __restrict__ bih,
                const float* __restrict__ bhh,
                float* __restrict__ out,
                int E)
{
    extern __shared__ uint32_t dsm[];
    float* gbuf = reinterpret_cast<float*>(dsm);

    const int tid  = threadIdx.x;
    const int lane = tid & 31;
    const int wid  = tid >> 5;
    const int wm   = wid & 1;
    const int g    = wid >> 1;
    const int row0 = (int)(blockIdx.x >> 3) * 64;
    const int n0   = (int)(blockIdx.x & 7) * 32;
    const uint32_t sbase = (uint32_t)__cvta_generic_to_shared(dsm);

    const int sub  = lane >> 3;
    const int lrow = lane & 7;
    const int aoffB = ((sub & 1) * 8 + lrow) * 144 + (sub >> 1) * 16;
    const int boffB = ((sub >> 1) * 8 + lrow) * 144 + (sub & 1) * 16;

    auto load_stage = [&](int st, int k0) {
        uint32_t sb = sbase + st * (GK_STAGE_H * 2);
        for (int f = tid; f < 1024; f += 384) {
            int which = f >> 9;
            int rem   = f & 511;
            int r     = rem >> 3;
            int ch    = (rem & 7) * 8;
            int gr    = row0 + r;
            const __half* src = which ? (g_x_h + (size_t)gr * H)
                                      : (g_agg_h + (size_t)gr * H);
            cp16(sb + ((which ? 4608 : 0) + r * 72 + ch) * 2, src + k0 + ch, gr < E);
        }
#pragma unroll
        for (int q = 0; q < 4; q++) {
            int f    = tid + q * 384;
            int g2   = f >> 8;
            int rem  = f & 255;
            int r    = rem >> 3;
            int ch   = (rem & 7) * 8;
            int gate = (g2 < 3) ? g2 : (g2 - 3);
            const __half* Wsrc = (g2 < 3) ? g_wih_h : g_whh_h;
            cp16(sb + (9216 + (g2 * 32 + r) * 72 + ch) * 2,
                 Wsrc + (size_t)(gate * H + n0 + r) * H + k0 + ch, true);
        }
        cp_commit();
    };

    float acc[2][4][4];
#pragma unroll
    for (int i = 0; i < 2; i++)
#pragma unroll
        for (int j = 0; j < 4; j++)
#pragma unroll
            for (int k = 0; k < 4; k++) acc[i][j][k] = 0.0f;

    load_stage(0, 0);

    for (int kc = 0; kc < 4; kc++) {
        cp_wait<0>();
        __syncthreads();
        if (kc < 3) load_stage((kc + 1) & 1, (kc + 1) * 64);

        const uint32_t Su = sbase + ((kc & 1) * GK_STAGE_H) * 2;
        const uint32_t Au = Su + ((g < 3) ? 0 : 4608) * 2;
        const uint32_t Bu = Su + 9216 * 2;

#pragma unroll
        for (int ks = 0; ks < 4; ks++) {
            int kb = ks * 32;
            uint32_t a[2][4], bb[2][4];
#pragma unroll
            for (int mi = 0; mi < 2; mi++)
                ldsm_x4(a[mi][0], a[mi][1], a[mi][2], a[mi][3],
                        Au + aoffB + (wm * 32 + mi * 16) * 144 + kb);
#pragma unroll
            for (int np = 0; np < 2; np++)
                ldsm_x4(bb[np][0], bb[np][1], bb[np][2], bb[np][3],
                        Bu + boffB + (g * 32 + np * 16) * 144 + kb);
#pragma unroll
            for (int mi = 0; mi < 2; mi++)
#pragma unroll
                for (int np = 0; np < 2; np++) {
                    mma_f16(acc[mi][2 * np],     a[mi], bb[np][0], bb[np][1]);
                    mma_f16(acc[mi][2 * np + 1], a[mi], bb[np][2], bb[np][3]);
                }
        }
    }

    __syncthreads();   // all warps done reading the ring before gbuf aliasing

    // ---- dump accumulators: gbuf[r][g*32 + c], row stride 192, float2 ----
#pragma unroll
    for (int mi = 0; mi < 2; mi++) {
        int r = wm * 32 + mi * 16 + (lane >> 2);
#pragma unroll
        for (int ni = 0; ni < 4; ni++) {
            int c = g * 32 + ni * 8 + 2 * (lane & 3);
            *reinterpret_cast<float2*>(&gbuf[r * 192 + c]) =
                make_float2(acc[mi][ni][0], acc[mi][ni][1]);
            *reinterpret_cast<float2*>(&gbuf[(r + 8) * 192 + c]) =
                make_float2(acc[mi][ni][2], acc[mi][ni][3]);
        }
    }
    __syncthreads();

    // ---- GRU gate math + output ----
    for (int idx = tid; idx < 64 * 32; idx += 384) {
        int r  = idx >> 5;
        int c  = idx & 31;
        int gr = row0 + r;
        if (gr >= E) continue;
        int gc = n0 + c;
        const float* gr_ = &gbuf[r * 192];
        float i_r = gr_[c]       + __ldg(&bih[gc]);
        float i_z = gr_[32 + c]  + __ldg(&bih[H + gc]);
        float i_n = gr_[64 + c]  + __ldg(&bih[2 * H + gc]);
        float h_r = gr_[96 + c]  + __ldg(&bhh[gc]);
        float h_z = gr_[128 + c] + __ldg(&bhh[H + gc]);
        float h_n = gr_[160 + c] + __ldg(&bhh[2 * H + gc]);

        float rg = sigmoidf_(i_r + h_r);
        float z  = sigmoidf_(i_z + h_z);
        float n  = tanhf(i_n + rg * h_n);
        float hp = __ldg(&X[(size_t)gr * H + gc]);
        out[(size_t)gr * H + gc] = (1.0f - z) * n + z * hp;
    }
}

// ============================================================================
extern "C" void kernel_launch(void* const* d_in, const int* in_sizes, int n_in,
                              void* d_out, int out_size)
{
    const float* X   = (const float*)d_in[0];
    const void*  ei  = d_in[1];
    const float* Wm  = (const float*)d_in[2];
    const float* bm  = (const float*)d_in[3];
    const float* Wih = (const float*)d_in[4];
    const float* Whh = (const float*)d_in[5];
    const float* bih = (const float*)d_in[6];
    const float* bhh = (const float*)d_in[7];
    float*       out = (float*)d_out;

    int E = in_sizes[0] / H;

    cudaFuncSetAttribute(msg_scatter_kernel,
                         cudaFuncAttributeMaxDynamicSharedMemorySize, 2 * MS_STAGE_H * 2);
    cudaFuncSetAttribute(gru_kernel,
                         cudaFuncAttributeMaxDynamicSharedMemorySize, 2 * GK_STAGE_H * 2);

    detect_idx_kernel<<<1, 256>>>((const int*)ei);                        // 1
    zero_agg_kernel<<<4096, 256>>>((E * H) / 8);                          // 2
    convert_inputs_kernel<<<4096, 256>>>(X, Wm, Wih, Whh, (E * H) / 4);   // 3

    int mrows = (E + 127) / 128;
    msg_scatter_kernel<<<mrows * 4, 256, 2 * MS_STAGE_H * 2>>>(ei, bm, E); // 4

    int grows = (E + 63) / 64;
    gru_kernel<<<grows * 8, 384, 2 * GK_STAGE_H * 2>>>(X, bih, bhh, out, E); // 5
}

// round 15
// speedup vs baseline: 1.4311x; 1.0168x over previous
#include <cuda_runtime.h>
#include <cuda_fp16.h>
#include <stdint.h>
#include <math.h>

#define H   256
#define EMAX 200000

// Scratch (allocation-free rule: static __device__).
__device__ __half g_agg_h[(size_t)EMAX * H];   // fp16 scatter target (RED.F16x2)
__device__ __half g_x_h[(size_t)EMAX * H];     // fp16 copy of edge_features
__device__ __half g_wm_h[H * H];
__device__ __half g_wih_h[3 * H * H];
__device__ __half g_whh_h[3 * H * H];
__device__ int g_idx_mode;                     // 1 = int64, 0 = int32

__device__ __forceinline__ void mma_f16(float c[4], const uint32_t a[4],
                                        uint32_t b0, uint32_t b1) {
    asm volatile(
        "mma.sync.aligned.m16n8k16.row.col.f32.f16.f16.f32 "
        "{%0,%1,%2,%3},{%4,%5,%6,%7},{%8,%9},{%0,%1,%2,%3};"
        : "+f"(c[0]), "+f"(c[1]), "+f"(c[2]), "+f"(c[3])
        : "r"(a[0]), "r"(a[1]), "r"(a[2]), "r"(a[3]), "r"(b0), "r"(b1));
}

__device__ __forceinline__ void ldsm_x4(uint32_t& r0, uint32_t& r1, uint32_t& r2, uint32_t& r3,
                                        uint32_t addr) {
    asm volatile("ldmatrix.sync.aligned.m8n8.x4.shared.b16 {%0,%1,%2,%3}, [%4];"
                 : "=r"(r0), "=r"(r1), "=r"(r2), "=r"(r3) : "r"(addr));
}

__device__ __forceinline__ float sigmoidf_(float x) {
    return 1.0f / (1.0f + __expf(-x));
}

__device__ __forceinline__ void cp16(uint32_t dst, const void* src, bool pred) {
    int sz = pred ? 16 : 0;
    asm volatile("cp.async.cg.shared.global [%0], [%1], 16, %2;\n"
                 :: "r"(dst), "l"(src), "r"(sz));
}
__device__ __forceinline__ void cp_commit() {
    asm volatile("cp.async.commit_group;\n");
}
template <int N>
__device__ __forceinline__ void cp_wait() {
    asm volatile("cp.async.wait_group %0;\n" :: "n"(N));
}

// ============================================================================
// Kernel A (launch 1): detect index dtype.
// ============================================================================
__global__ void detect_idx_kernel(const int* __restrict__ idx32)
{
    __shared__ int ored[256];
    int t = threadIdx.x;
    ored[t] = idx32[2 * t + 1];
    __syncthreads();
    for (int s = 128; s > 0; s >>= 1) {
        if (t < s) ored[t] |= ored[t + s];
        __syncthreads();
    }
    if (t == 0) g_idx_mode = (ored[0] == 0) ? 1 : 0;
}

// ============================================================================
// fp32 -> fp16 segment converter (device helper)
// ============================================================================
__device__ __forceinline__ void conv_seg(const float* __restrict__ src,
                                         __half* __restrict__ dst, int n4,
                                         int idx, int stride)
{
    const float4* s4 = (const float4*)src;
    uint2* d4 = (uint2*)dst;
    for (int i = idx; i < n4; i += stride) {
        float4 v = s4[i];
        __half2 h0 = __floats2half2_rn(v.x, v.y);
        __half2 h1 = __floats2half2_rn(v.z, v.w);
        uint2 o;
        o.x = *reinterpret_cast<uint32_t*>(&h0);
        o.y = *reinterpret_cast<uint32_t*>(&h1);
        d4[i] = o;
    }
}

// Kernel B (launch 2): zero fp16 agg + convert X and all weights, ONE launch.
__global__ void prep_kernel(const float* __restrict__ X,
                            const float* __restrict__ Wm,
                            const float* __restrict__ Wih,
                            const float* __restrict__ Whh,
                            int exh4)
{
    int idx = blockIdx.x * blockDim.x + threadIdx.x;
    int stride = gridDim.x * blockDim.x;

    // zero g_agg_h: exh4/2 uint4 stores (8 halves each)
    uint4* az = reinterpret_cast<uint4*>(g_agg_h);
    uint4 z = make_uint4(0, 0, 0, 0);
    int n8 = exh4 >> 1;
    for (int i = idx; i < n8; i += stride) az[i] = z;

    conv_seg(X,   g_x_h,   exh4,            idx, stride);
    conv_seg(Wm,  g_wm_h,  (H * H) / 4,     idx, stride);
    conv_seg(Wih, g_wih_h, (3 * H * H) / 4, idx, stride);
    conv_seg(Whh, g_whh_h, (3 * H * H) / 4, idx, stride);
}

// ============================================================================
// Kernel 1 (launch 3): message = relu(X16 @ Wm16^T + b); RED.F16x2 scatter.
// fp16 m16n8k16. Tile 128x64, kchunk 64 (4 ksteps), 2-stage, 1 sync/chunk.
// __launch_bounds__(256,3): force <=83 regs -> 3 blocks/SM (occ 23% -> ~34%)
// for this latency-bound (RED + cp.async) kernel.
// Stage (halves): A[128*72]=9216 @0, B[64*72]=4608 @9216. Stage = 13824 h.
// ============================================================================
#define MS_STAGE_H 13824

__global__ __launch_bounds__(256, 3)
void msg_scatter_kernel(const void* __restrict__ eidx,
                        const float* __restrict__ bias,
                        int E)
{
    extern __shared__ uint32_t dsm[];
    __shared__ int dsts[128];

    const int tid  = threadIdx.x;
    const int lane = tid & 31;
    const int wid  = tid >> 5;
    const int wm   = wid & 3;
    const int wn   = wid >> 2;
    const int row0 = (int)(blockIdx.x >> 2) * 128;
    const int n0   = (int)(blockIdx.x & 3) * 64;
    const uint32_t sbase = (uint32_t)__cvta_generic_to_shared(dsm);

    const int sub  = lane >> 3;
    const int lrow = lane & 7;
    const int aoffB = ((sub & 1) * 8 + lrow) * 144 + (sub >> 1) * 16;
    const int boffB = ((sub >> 1) * 8 + lrow) * 144 + (sub & 1) * 16;

    if (tid < 128) {
        int r = row0 + tid;
        int d = -1;
        if (r < E) {
            d = g_idx_mode ? (int)((const long long*)eidx)[(size_t)E + r]
                           : ((const int*)eidx)[(size_t)E + r];
            if (d < 0 || d >= E) d = -1;
        }
        dsts[tid] = d;
    }

    auto load_stage = [&](int st, int k0) {
        uint32_t sb = sbase + st * (MS_STAGE_H * 2);
#pragma unroll
        for (int q = 0; q < 4; q++) {
            int f  = tid + q * 256;
            int r  = f >> 3;
            int ch = (f & 7) * 8;
            int gr = row0 + r;
            cp16(sb + (r * 72 + ch) * 2, g_x_h + (size_t)gr * H + k0 + ch, gr < E);
        }
#pragma unroll
        for (int q = 0; q < 2; q++) {
            int f  = tid + q * 256;
            int r  = f >> 3;
            int ch = (f & 7) * 8;
            cp16(sb + (9216 + r * 72 + ch) * 2,
                 g_wm_h + (size_t)(n0 + r) * H + k0 + ch, true);
        }
        cp_commit();
    };

    float acc[2][4][4];
#pragma unroll
    for (int i = 0; i < 2; i++)
#pragma unroll
        for (int j = 0; j < 4; j++)
#pragma unroll
            for (int k = 0; k < 4; k++) acc[i][j][k] = 0.0f;

    load_stage(0, 0);

    for (int kc = 0; kc < 4; kc++) {
        cp_wait<0>();
        __syncthreads();
        if (kc < 3) load_stage((kc + 1) & 1, (kc + 1) * 64);

        const uint32_t Au = sbase + ((kc & 1) * MS_STAGE_H) * 2;
        const uint32_t Bu = Au + 9216 * 2;

#pragma unroll
        for (int ks = 0; ks < 4; ks++) {
            int kb = ks * 32;
            uint32_t a[2][4], bb[2][4];
#pragma unroll
            for (int mi = 0; mi < 2; mi++)
                ldsm_x4(a[mi][0], a[mi][1], a[mi][2], a[mi][3],
                        Au + aoffB + (wm * 32 + mi * 16) * 144 + kb);
#pragma unroll
            for (int np = 0; np < 2; np++)
                ldsm_x4(bb[np][0], bb[np][1], bb[np][2], bb[np][3],
                        Bu + boffB + (wn * 32 + np * 16) * 144 + kb);
#pragma unroll
            for (int mi = 0; mi < 2; mi++)
#pragma unroll
                for (int np = 0; np < 2; np++) {
                    mma_f16(acc[mi][2 * np],     a[mi], bb[np][0], bb[np][1]);
                    mma_f16(acc[mi][2 * np + 1], a[mi], bb[np][2], bb[np][3]);
                }
        }
    }

    // ---- epilogue: bias + relu + fp16x2 vector atomics (RED.ADD.F16x2) ----
#pragma unroll
    for (int mi = 0; mi < 2; mi++) {
#pragma unroll
        for (int half = 0; half < 2; half++) {
            int rl = wm * 32 + mi * 16 + (lane >> 2) + half * 8;
            int d  = dsts[rl];
            if (d < 0) continue;
            size_t base = (size_t)d * H;
#pragma unroll
            for (int ni = 0; ni < 4; ni++) {
                int col  = n0 + wn * 32 + ni * 8 + 2 * (lane & 3);
                float v0 = fmaxf(acc[mi][ni][half * 2 + 0] + __ldg(&bias[col]), 0.0f);
                float v1 = fmaxf(acc[mi][ni][half * 2 + 1] + __ldg(&bias[col + 1]), 0.0f);
                __half2 hv = __floats2half2_rn(v0, v1);
                atomicAdd(reinterpret_cast<__half2*>(&g_agg_h[base + col]), hv);
            }
        }
    }
}

// ============================================================================
// Kernel 2 (launch 4): GRU fused GEMMs, fp16, kchunk 64, 1 sync/chunk.
// (byte-identical to round 14)
// ============================================================================
#define GK_STAGE_H 23040

__global__ __launch_bounds__(384, 2)
void gru_kernel(const float* __restrict__ X,
                const float* __restrict__ bih,
                const float* __restrict__ bhh,
                float* __restrict__ out,
                int E)
{
    extern __shared__ uint32_t dsm[];
    float* gbuf = reinterpret_cast<float*>(dsm);

    const int tid  = threadIdx.x;
    const int lane = tid & 31;
    const int wid  = tid >> 5;
    const int wm   = wid & 1;
    const int g    = wid >> 1;
    const int row0 = (int)(blockIdx.x >> 3) * 64;
    const int n0   = (int)(blockIdx.x & 7) * 32;
    const uint32_t sbase = (uint32_t)__cvta_generic_to_shared(dsm);

    const int sub  = lane >> 3;
    const int lrow = lane & 7;
    const int aoffB = ((sub & 1) * 8 + lrow) * 144 + (sub >> 1) * 16;
    const int boffB = ((sub >> 1) * 8 + lrow) * 144 + (sub & 1) * 16;

    auto load_stage = [&](int st, int k0) {
        uint32_t sb = sbase + st * (GK_STAGE_H * 2);
        for (int f = tid; f < 1024; f += 384) {
            int which = f >> 9;
            int rem   = f & 511;
            int r     = rem >> 3;
            int ch    = (rem & 7) * 8;
            int gr    = row0 + r;
            const __half* src = which ? (g_x_h + (size_t)gr * H)
                                      : (g_agg_h + (size_t)gr * H);
            cp16(sb + ((which ? 4608 : 0) + r * 72 + ch) * 2, src + k0 + ch, gr < E);
        }
#pragma unroll
        for (int q = 0; q < 4; q++) {
            int f    = tid + q * 384;
            int g2   = f >> 8;
            int rem  = f & 255;
            int r    = rem >> 3;
            int ch   = (rem & 7) * 8;
            int gate = (g2 < 3) ? g2 : (g2 - 3);
            const __half* Wsrc = (g2 < 3) ? g_wih_h : g_whh_h;
            cp16(sb + (9216 + (g2 * 32 + r) * 72 + ch) * 2,
                 Wsrc + (size_t)(gate * H + n0 + r) * H + k0 + ch, true);
        }
        cp_commit();
    };

    float acc[2][4][4];
#pragma unroll
    for (int i = 0; i < 2; i++)
#pragma unroll
        for (int j = 0; j < 4; j++)
#pragma unroll
            for (int k = 0; k < 4; k++) acc[i][j][k] = 0.0f;

    load_stage(0, 0);

    for (int kc = 0; kc < 4; kc++) {
        cp_wait<0>();
        __syncthreads();
        if (kc < 3) load_stage((kc + 1) & 1, (kc + 1) * 64);

        const uint32_t Su = sbase + ((kc & 1) * GK_STAGE_H) * 2;
        const uint32_t Au = Su + ((g < 3) ? 0 : 4608) * 2;
        const uint32_t Bu = Su + 9216 * 2;

#pragma unroll
        for (int ks = 0; ks < 4; ks++) {
            int kb = ks * 32;
            uint32_t a[2][4], bb[2][4];
#pragma unroll
            for (int mi = 0; mi < 2; mi++)
                ldsm_x4(a[mi][0], a[mi][1], a[mi][2], a[mi][3],
                        Au + aoffB + (wm * 32 + mi * 16) * 144 + kb);
#pragma unroll
            for (int np = 0; np < 2; np++)
                ldsm_x4(bb[np][0], bb[np][1], bb[np][2], bb[np][3],
                        Bu + boffB + (g * 32 + np * 16) * 144 + kb);
#pragma unroll
            for (int mi = 0; mi < 2; mi++)
#pragma unroll
                for (int np = 0; np < 2; np++) {
                    mma_f16(acc[mi][2 * np],     a[mi], bb[np][0], bb[np][1]);
                    mma_f16(acc[mi][2 * np + 1], a[mi], bb[np][2], bb[np][3]);
                }
        }
    }

    __syncthreads();   // all warps done reading the ring before gbuf aliasing

    // ---- dump accumulators: gbuf[r][g*32 + c], row stride 192, float2 ----
#pragma unroll
    for (int mi = 0; mi < 2; mi++) {
        int r = wm * 32 + mi * 16 + (lane >> 2);
#pragma unroll
        for (int ni = 0; ni < 4; ni++) {
            int c = g * 32 + ni * 8 + 2 * (lane & 3);
            *reinterpret_cast<float2*>(&gbuf[r * 192 + c]) =
                make_float2(acc[mi][ni][0], acc[mi][ni][1]);
            *reinterpret_cast<float2*>(&gbuf[(r + 8) * 192 + c]) =
                make_float2(acc[mi][ni][2], acc[mi][ni][3]);
        }
    }
    __syncthreads();

    // ---- GRU gate math + output ----
    for (int idx = tid; idx < 64 * 32; idx += 384) {
        int r  = idx >> 5;
        int c  = idx & 31;
        int gr = row0 + r;
        if (gr >= E) continue;
        int gc = n0 + c;
        const float* gr_ = &gbuf[r * 192];
        float i_r = gr_[c]       + __ldg(&bih[gc]);
        float i_z = gr_[32 + c]  + __ldg(&bih[H + gc]);
        float i_n = gr_[64 + c]  + __ldg(&bih[2 * H + gc]);
        float h_r = gr_[96 + c]  + __ldg(&bhh[gc]);
        float h_z = gr_[128 + c] + __ldg(&bhh[H + gc]);
        float h_n = gr_[160 + c] + __ldg(&bhh[2 * H + gc]);

        float rg = sigmoidf_(i_r + h_r);
        float z  = sigmoidf_(i_z + h_z);
        float n  = tanhf(i_n + rg * h_n);
        float hp = __ldg(&X[(size_t)gr * H + gc]);
        out[(size_t)gr * H + gc] = (1.0f - z) * n + z * hp;
    }
}

// ============================================================================
extern "C" void kernel_launch(void* const* d_in, const int* in_sizes, int n_in,
                              void* d_out, int out_size)
{
    const float* X   = (const float*)d_in[0];
    const void*  ei  = d_in[1];
    const float* Wm  = (const float*)d_in[2];
    const float* bm  = (const float*)d_in[3];
    const float* Wih = (const float*)d_in[4];
    const float* Whh = (const float*)d_in[5];
    const float* bih = (const float*)d_in[6];
    const float* bhh = (const float*)d_in[7];
    float*       out = (float*)d_out;

    int E = in_sizes[0] / H;

    cudaFuncSetAttribute(msg_scatter_kernel,
                         cudaFuncAttributeMaxDynamicSharedMemorySize, 2 * MS_STAGE_H * 2);
    cudaFuncSetAttribute(gru_kernel,
                         cudaFuncAttributeMaxDynamicSharedMemorySize, 2 * GK_STAGE_H * 2);

    detect_idx_kernel<<<1, 256>>>((const int*)ei);                        // 1
    prep_kernel<<<4096, 256>>>(X, Wm, Wih, Whh, (E * H) / 4);             // 2 (zero+convert)

    int mrows = (E + 127) / 128;
    msg_scatter_kernel<<<mrows * 4, 256, 2 * MS_STAGE_H * 2>>>(ei, bm, E); // 3

    int grows = (E + 63) / 64;
    gru_kernel<<<grows * 8, 384, 2 * GK_STAGE_H * 2>>>(X, bih, bhh, out, E); // 4
}

// round 16
// speedup vs baseline: 1.6675x; 1.1652x over previous
#include <cuda_runtime.h>
#include <cuda_fp16.h>
#include <stdint.h>
#include <math.h>

#define H   256
#define EMAX 200000

// Scratch (allocation-free rule: static __device__).
__device__ __half g_agg_h[(size_t)EMAX * H];   // fp16 scatter target (RED.F16x2)
__device__ __half g_x_h[(size_t)EMAX * H];     // fp16 copy of edge_features
__device__ __half g_wm_h[H * H];
__device__ __half g_wih_h[3 * H * H];
__device__ __half g_whh_h[3 * H * H];
__device__ int g_idx_mode;                     // 1 = int64, 0 = int32

__device__ __forceinline__ void mma_f16(float c[4], const uint32_t a[4],
                                        uint32_t b0, uint32_t b1) {
    asm volatile(
        "mma.sync.aligned.m16n8k16.row.col.f32.f16.f16.f32 "
        "{%0,%1,%2,%3},{%4,%5,%6,%7},{%8,%9},{%0,%1,%2,%3};"
        : "+f"(c[0]), "+f"(c[1]), "+f"(c[2]), "+f"(c[3])
        : "r"(a[0]), "r"(a[1]), "r"(a[2]), "r"(a[3]), "r"(b0), "r"(b1));
}

__device__ __forceinline__ void ldsm_x4(uint32_t& r0, uint32_t& r1, uint32_t& r2, uint32_t& r3,
                                        uint32_t addr) {
    asm volatile("ldmatrix.sync.aligned.m8n8.x4.shared.b16 {%0,%1,%2,%3}, [%4];"
                 : "=r"(r0), "=r"(r1), "=r"(r2), "=r"(r3) : "r"(addr));
}

// fast activations: HW MUFU tanh; sigmoid via EX2.approx + RCP.approx
__device__ __forceinline__ float tanh_fast(float x) {
    float r;
    asm("tanh.approx.f32 %0, %1;" : "=f"(r) : "f"(x));
    return r;
}
__device__ __forceinline__ float sigmoid_fast(float x) {
    return __fdividef(1.0f, 1.0f + __expf(-x));
}

__device__ __forceinline__ void cp16(uint32_t dst, const void* src, bool pred) {
    int sz = pred ? 16 : 0;
    asm volatile("cp.async.cg.shared.global [%0], [%1], 16, %2;\n"
                 :: "r"(dst), "l"(src), "r"(sz));
}
__device__ __forceinline__ void cp_commit() {
    asm volatile("cp.async.commit_group;\n");
}
template <int N>
__device__ __forceinline__ void cp_wait() {
    asm volatile("cp.async.wait_group %0;\n" :: "n"(N));
}

// ============================================================================
// Kernel A (launch 1): detect index dtype.
// ============================================================================
__global__ void detect_idx_kernel(const int* __restrict__ idx32)
{
    __shared__ int ored[256];
    int t = threadIdx.x;
    ored[t] = idx32[2 * t + 1];
    __syncthreads();
    for (int s = 128; s > 0; s >>= 1) {
        if (t < s) ored[t] |= ored[t + s];
        __syncthreads();
    }
    if (t == 0) g_idx_mode = (ored[0] == 0) ? 1 : 0;
}

// ============================================================================
// fp32 -> fp16 segment converter (device helper)
// ============================================================================
__device__ __forceinline__ void conv_seg(const float* __restrict__ src,
                                         __half* __restrict__ dst, int n4,
                                         int idx, int stride)
{
    const float4* s4 = (const float4*)src;
    uint2* d4 = (uint2*)dst;
    for (int i = idx; i < n4; i += stride) {
        float4 v = s4[i];
        __half2 h0 = __floats2half2_rn(v.x, v.y);
        __half2 h1 = __floats2half2_rn(v.z, v.w);
        uint2 o;
        o.x = *reinterpret_cast<uint32_t*>(&h0);
        o.y = *reinterpret_cast<uint32_t*>(&h1);
        d4[i] = o;
    }
}

// Kernel B (launch 2): zero fp16 agg + convert X and all weights, ONE launch.
__global__ void prep_kernel(const float* __restrict__ X,
                            const float* __restrict__ Wm,
                            const float* __restrict__ Wih,
                            const float* __restrict__ Whh,
                            int exh4)
{
    int idx = blockIdx.x * blockDim.x + threadIdx.x;
    int stride = gridDim.x * blockDim.x;

    uint4* az = reinterpret_cast<uint4*>(g_agg_h);
    uint4 z = make_uint4(0, 0, 0, 0);
    int n8 = exh4 >> 1;
    for (int i = idx; i < n8; i += stride) az[i] = z;

    conv_seg(X,   g_x_h,   exh4,            idx, stride);
    conv_seg(Wm,  g_wm_h,  (H * H) / 4,     idx, stride);
    conv_seg(Wih, g_wih_h, (3 * H * H) / 4, idx, stride);
    conv_seg(Whh, g_whh_h, (3 * H * H) / 4, idx, stride);
}

// ============================================================================
// Kernel 1 (launch 3): message = relu(X16 @ Wm16^T + b); RED.F16x2 scatter.
// (byte-identical to round 15)
// ============================================================================
#define MS_STAGE_H 13824

__global__ __launch_bounds__(256, 3)
void msg_scatter_kernel(const void* __restrict__ eidx,
                        const float* __restrict__ bias,
                        int E)
{
    extern __shared__ uint32_t dsm[];
    __shared__ int dsts[128];

    const int tid  = threadIdx.x;
    const int lane = tid & 31;
    const int wid  = tid >> 5;
    const int wm   = wid & 3;
    const int wn   = wid >> 2;
    const int row0 = (int)(blockIdx.x >> 2) * 128;
    const int n0   = (int)(blockIdx.x & 3) * 64;
    const uint32_t sbase = (uint32_t)__cvta_generic_to_shared(dsm);

    const int sub  = lane >> 3;
    const int lrow = lane & 7;
    const int aoffB = ((sub & 1) * 8 + lrow) * 144 + (sub >> 1) * 16;
    const int boffB = ((sub >> 1) * 8 + lrow) * 144 + (sub & 1) * 16;

    if (tid < 128) {
        int r = row0 + tid;
        int d = -1;
        if (r < E) {
            d = g_idx_mode ? (int)((const long long*)eidx)[(size_t)E + r]
                           : ((const int*)eidx)[(size_t)E + r];
            if (d < 0 || d >= E) d = -1;
        }
        dsts[tid] = d;
    }

    auto load_stage = [&](int st, int k0) {
        uint32_t sb = sbase + st * (MS_STAGE_H * 2);
#pragma unroll
        for (int q = 0; q < 4; q++) {
            int f  = tid + q * 256;
            int r  = f >> 3;
            int ch = (f & 7) * 8;
            int gr = row0 + r;
            cp16(sb + (r * 72 + ch) * 2, g_x_h + (size_t)gr * H + k0 + ch, gr < E);
        }
#pragma unroll
        for (int q = 0; q < 2; q++) {
            int f  = tid + q * 256;
            int r  = f >> 3;
            int ch = (f & 7) * 8;
            cp16(sb + (9216 + r * 72 + ch) * 2,
                 g_wm_h + (size_t)(n0 + r) * H + k0 + ch, true);
        }
        cp_commit();
    };

    float acc[2][4][4];
#pragma unroll
    for (int i = 0; i < 2; i++)
#pragma unroll
        for (int j = 0; j < 4; j++)
#pragma unroll
            for (int k = 0; k < 4; k++) acc[i][j][k] = 0.0f;

    load_stage(0, 0);

    for (int kc = 0; kc < 4; kc++) {
        cp_wait<0>();
        __syncthreads();
        if (kc < 3) load_stage((kc + 1) & 1, (kc + 1) * 64);

        const uint32_t Au = sbase + ((kc & 1) * MS_STAGE_H) * 2;
        const uint32_t Bu = Au + 9216 * 2;

#pragma unroll
        for (int ks = 0; ks < 4; ks++) {
            int kb = ks * 32;
            uint32_t a[2][4], bb[2][4];
#pragma unroll
            for (int mi = 0; mi < 2; mi++)
                ldsm_x4(a[mi][0], a[mi][1], a[mi][2], a[mi][3],
                        Au + aoffB + (wm * 32 + mi * 16) * 144 + kb);
#pragma unroll
            for (int np = 0; np < 2; np++)
                ldsm_x4(bb[np][0], bb[np][1], bb[np][2], bb[np][3],
                        Bu + boffB + (wn * 32 + np * 16) * 144 + kb);
#pragma unroll
            for (int mi = 0; mi < 2; mi++)
#pragma unroll
                for (int np = 0; np < 2; np++) {
                    mma_f16(acc[mi][2 * np],     a[mi], bb[np][0], bb[np][1]);
                    mma_f16(acc[mi][2 * np + 1], a[mi], bb[np][2], bb[np][3]);
                }
        }
    }

#pragma unroll
    for (int mi = 0; mi < 2; mi++) {
#pragma unroll
        for (int half = 0; half < 2; half++) {
            int rl = wm * 32 + mi * 16 + (lane >> 2) + half * 8;
            int d  = dsts[rl];
            if (d < 0) continue;
            size_t base = (size_t)d * H;
#pragma unroll
            for (int ni = 0; ni < 4; ni++) {
                int col  = n0 + wn * 32 + ni * 8 + 2 * (lane & 3);
                float v0 = fmaxf(acc[mi][ni][half * 2 + 0] + __ldg(&bias[col]), 0.0f);
                float v1 = fmaxf(acc[mi][ni][half * 2 + 1] + __ldg(&bias[col + 1]), 0.0f);
                __half2 hv = __floats2half2_rn(v0, v1);
                atomicAdd(reinterpret_cast<__half2*>(&g_agg_h[base + col]), hv);
            }
        }
    }
}

// ============================================================================
// Kernel 2 (launch 4): GRU fused GEMMs. Mainloop identical to round 15;
// epilogue rewritten: float2-vectorized, tanh.approx + fast sigmoid.
// ============================================================================
#define GK_STAGE_H 23040

__global__ __launch_bounds__(384, 2)
void gru_kernel(const float* __restrict__ X,
                const float* __restrict__ bih,
                const float* __restrict__ bhh,
                float* __restrict__ out,
                int E)
{
    extern __shared__ uint32_t dsm[];
    float* gbuf = reinterpret_cast<float*>(dsm);

    const int tid  = threadIdx.x;
    const int lane = tid & 31;
    const int wid  = tid >> 5;
    const int wm   = wid & 1;
    const int g    = wid >> 1;
    const int row0 = (int)(blockIdx.x >> 3) * 64;
    const int n0   = (int)(blockIdx.x & 7) * 32;
    const uint32_t sbase = (uint32_t)__cvta_generic_to_shared(dsm);

    const int sub  = lane >> 3;
    const int lrow = lane & 7;
    const int aoffB = ((sub & 1) * 8 + lrow) * 144 + (sub >> 1) * 16;
    const int boffB = ((sub >> 1) * 8 + lrow) * 144 + (sub & 1) * 16;

    auto load_stage = [&](int st, int k0) {
        uint32_t sb = sbase + st * (GK_STAGE_H * 2);
        for (int f = tid; f < 1024; f += 384) {
            int which = f >> 9;
            int rem   = f & 511;
            int r     = rem >> 3;
            int ch    = (rem & 7) * 8;
            int gr    = row0 + r;
            const __half* src = which ? (g_x_h + (size_t)gr * H)
                                      : (g_agg_h + (size_t)gr * H);
            cp16(sb + ((which ? 4608 : 0) + r * 72 + ch) * 2, src + k0 + ch, gr < E);
        }
#pragma unroll
        for (int q = 0; q < 4; q++) {
            int f    = tid + q * 384;
            int g2   = f >> 8;
            int rem  = f & 255;
            int r    = rem >> 3;
            int ch   = (rem & 7) * 8;
            int gate = (g2 < 3) ? g2 : (g2 - 3);
            const __half* Wsrc = (g2 < 3) ? g_wih_h : g_whh_h;
            cp16(sb + (9216 + (g2 * 32 + r) * 72 + ch) * 2,
                 Wsrc + (size_t)(gate * H + n0 + r) * H + k0 + ch, true);
        }
        cp_commit();
    };

    float acc[2][4][4];
#pragma unroll
    for (int i = 0; i < 2; i++)
#pragma unroll
        for (int j = 0; j < 4; j++)
#pragma unroll
            for (int k = 0; k < 4; k++) acc[i][j][k] = 0.0f;

    load_stage(0, 0);

    for (int kc = 0; kc < 4; kc++) {
        cp_wait<0>();
        __syncthreads();
        if (kc < 3) load_stage((kc + 1) & 1, (kc + 1) * 64);

        const uint32_t Su = sbase + ((kc & 1) * GK_STAGE_H) * 2;
        const uint32_t Au = Su + ((g < 3) ? 0 : 4608) * 2;
        const uint32_t Bu = Su + 9216 * 2;

#pragma unroll
        for (int ks = 0; ks < 4; ks++) {
            int kb = ks * 32;
            uint32_t a[2][4], bb[2][4];
#pragma unroll
            for (int mi = 0; mi < 2; mi++)
                ldsm_x4(a[mi][0], a[mi][1], a[mi][2], a[mi][3],
                        Au + aoffB + (wm * 32 + mi * 16) * 144 + kb);
#pragma unroll
            for (int np = 0; np < 2; np++)
                ldsm_x4(bb[np][0], bb[np][1], bb[np][2], bb[np][3],
                        Bu + boffB + (g * 32 + np * 16) * 144 + kb);
#pragma unroll
            for (int mi = 0; mi < 2; mi++)
#pragma unroll
                for (int np = 0; np < 2; np++) {
                    mma_f16(acc[mi][2 * np],     a[mi], bb[np][0], bb[np][1]);
                    mma_f16(acc[mi][2 * np + 1], a[mi], bb[np][2], bb[np][3]);
                }
        }
    }

    __syncthreads();   // all warps done reading the ring before gbuf aliasing

    // ---- dump accumulators: gbuf[r][g*32 + c], row stride 192, float2 ----
#pragma unroll
    for (int mi = 0; mi < 2; mi++) {
        int r = wm * 32 + mi * 16 + (lane >> 2);
#pragma unroll
        for (int ni = 0; ni < 4; ni++) {
            int c = g * 32 + ni * 8 + 2 * (lane & 3);
            *reinterpret_cast<float2*>(&gbuf[r * 192 + c]) =
                make_float2(acc[mi][ni][0], acc[mi][ni][1]);
            *reinterpret_cast<float2*>(&gbuf[(r + 8) * 192 + c]) =
                make_float2(acc[mi][ni][2], acc[mi][ni][3]);
        }
    }
    __syncthreads();

    // ---- GRU gate math + output: float2-vectorized, fast activations ----
    // 64 rows x 16 col-pairs = 1024 iters / 384 threads
    for (int idx = tid; idx < 64 * 16; idx += 384) {
        int r  = idx >> 4;
        int c  = (idx & 15) * 2;
        int gr = row0 + r;
        if (gr >= E) continue;
        int gc = n0 + c;
        const float* gr_ = &gbuf[r * 192];

        float2 xir = *reinterpret_cast<const float2*>(gr_ + c);
        float2 xiz = *reinterpret_cast<const float2*>(gr_ + 32 + c);
        float2 xin = *reinterpret_cast<const float2*>(gr_ + 64 + c);
        float2 xhr = *reinterpret_cast<const float2*>(gr_ + 96 + c);
        float2 xhz = *reinterpret_cast<const float2*>(gr_ + 128 + c);
        float2 xhn = *reinterpret_cast<const float2*>(gr_ + 160 + c);

        float2 bir = *reinterpret_cast<const float2*>(bih + gc);
        float2 biz = *reinterpret_cast<const float2*>(bih + H + gc);
        float2 bin = *reinterpret_cast<const float2*>(bih + 2 * H + gc);
        float2 bhr = *reinterpret_cast<const float2*>(bhh + gc);
        float2 bhz = *reinterpret_cast<const float2*>(bhh + H + gc);
        float2 bhn = *reinterpret_cast<const float2*>(bhh + 2 * H + gc);

        float2 hp = *reinterpret_cast<const float2*>(X + (size_t)gr * H + gc);

        float2 o;
        {
            float rg = sigmoid_fast(xir.x + bir.x + xhr.x + bhr.x);
            float z  = sigmoid_fast(xiz.x + biz.x + xhz.x + bhz.x);
            float n  = tanh_fast(xin.x + bin.x + rg * (xhn.x + bhn.x));
            o.x = (1.0f - z) * n + z * hp.x;
        }
        {
            float rg = sigmoid_fast(xir.y + bir.y + xhr.y + bhr.y);
            float z  = sigmoid_fast(xiz.y + biz.y + xhz.y + bhz.y);
            float n  = tanh_fast(xin.y + bin.y + rg * (xhn.y + bhn.y));
            o.y = (1.0f - z) * n + z * hp.y;
        }
        *reinterpret_cast<float2*>(out + (size_t)gr * H + gc) = o;
    }
}

// ============================================================================
extern "C" void kernel_launch(void* const* d_in, const int* in_sizes, int n_in,
                              void* d_out, int out_size)
{
    const float* X   = (const float*)d_in[0];
    const void*  ei  = d_in[1];
    const float* Wm  = (const float*)d_in[2];
    const float* bm  = (const float*)d_in[3];
    const float* Wih = (const float*)d_in[4];
    const float* Whh = (const float*)d_in[5];
    const float* bih = (const float*)d_in[6];
    const float* bhh = (const float*)d_in[7];
    float*       out = (float*)d_out;

    int E = in_sizes[0] / H;

    cudaFuncSetAttribute(msg_scatter_kernel,
                         cudaFuncAttributeMaxDynamicSharedMemorySize, 2 * MS_STAGE_H * 2);
    cudaFuncSetAttribute(gru_kernel,
                         cudaFuncAttributeMaxDynamicSharedMemorySize, 2 * GK_STAGE_H * 2);

    detect_idx_kernel<<<1, 256>>>((const int*)ei);                        // 1
    prep_kernel<<<4096, 256>>>(X, Wm, Wih, Whh, (E * H) / 4);             // 2

    int mrows = (E + 127) / 128;
    msg_scatter_kernel<<<mrows * 4, 256, 2 * MS_STAGE_H * 2>>>(ei, bm, E); // 3

    int grows = (E + 63) / 64;
    gru_kernel<<<grows * 8, 384, 2 * GK_STAGE_H * 2>>>(X, bih, bhh, out, E); // 4
}

// round 17
// speedup vs baseline: 1.8644x; 1.1180x over previous
#include <cuda_runtime.h>
#include <cuda_fp16.h>
#include <stdint.h>
#include <math.h>

#define H   256
#define EMAX 200000

// Scratch (allocation-free rule: static __device__).
__device__ __half g_agg_h[(size_t)EMAX * H];   // fp16 scatter target (RED.F16x2)
__device__ __half g_x_h[(size_t)EMAX * H];     // fp16 copy of edge_features
__device__ __half g_wm_h[H * H];
__device__ __half g_wih_h[3 * H * H];
__device__ __half g_whh_h[3 * H * H];
__device__ int g_idx_mode;                     // 1 = int64, 0 = int32

__device__ __forceinline__ void mma_f16(float c[4], const uint32_t a[4],
                                        uint32_t b0, uint32_t b1) {
    asm volatile(
        "mma.sync.aligned.m16n8k16.row.col.f32.f16.f16.f32 "
        "{%0,%1,%2,%3},{%4,%5,%6,%7},{%8,%9},{%0,%1,%2,%3};"
        : "+f"(c[0]), "+f"(c[1]), "+f"(c[2]), "+f"(c[3])
        : "r"(a[0]), "r"(a[1]), "r"(a[2]), "r"(a[3]), "r"(b0), "r"(b1));
}

__device__ __forceinline__ void ldsm_x4(uint32_t& r0, uint32_t& r1, uint32_t& r2, uint32_t& r3,
                                        uint32_t addr) {
    asm volatile("ldmatrix.sync.aligned.m8n8.x4.shared.b16 {%0,%1,%2,%3}, [%4];"
                 : "=r"(r0), "=r"(r1), "=r"(r2), "=r"(r3) : "r"(addr));
}

// fast activations: HW MUFU tanh; sigmoid via EX2.approx + RCP.approx
__device__ __forceinline__ float tanh_fast(float x) {
    float r;
    asm("tanh.approx.f32 %0, %1;" : "=f"(r) : "f"(x));
    return r;
}
__device__ __forceinline__ float sigmoid_fast(float x) {
    return __fdividef(1.0f, 1.0f + __expf(-x));
}

__device__ __forceinline__ void cp16(uint32_t dst, const void* src, bool pred) {
    int sz = pred ? 16 : 0;
    asm volatile("cp.async.cg.shared.global [%0], [%1], 16, %2;\n"
                 :: "r"(dst), "l"(src), "r"(sz));
}
__device__ __forceinline__ void cp_commit() {
    asm volatile("cp.async.commit_group;\n");
}
template <int N>
__device__ __forceinline__ void cp_wait() {
    asm volatile("cp.async.wait_group %0;\n" :: "n"(N));
}

// ============================================================================
// Kernel A (launch 1): detect index dtype.
// ============================================================================
__global__ void detect_idx_kernel(const int* __restrict__ idx32)
{
    __shared__ int ored[256];
    int t = threadIdx.x;
    ored[t] = idx32[2 * t + 1];
    __syncthreads();
    for (int s = 128; s > 0; s >>= 1) {
        if (t < s) ored[t] |= ored[t + s];
        __syncthreads();
    }
    if (t == 0) g_idx_mode = (ored[0] == 0) ? 1 : 0;
}

// ============================================================================
// fp32 -> fp16 segment converter (device helper)
// ============================================================================
__device__ __forceinline__ void conv_seg(const float* __restrict__ src,
                                         __half* __restrict__ dst, int n4,
                                         int idx, int stride)
{
    const float4* s4 = (const float4*)src;
    uint2* d4 = (uint2*)dst;
    for (int i = idx; i < n4; i += stride) {
        float4 v = s4[i];
        __half2 h0 = __floats2half2_rn(v.x, v.y);
        __half2 h1 = __floats2half2_rn(v.z, v.w);
        uint2 o;
        o.x = *reinterpret_cast<uint32_t*>(&h0);
        o.y = *reinterpret_cast<uint32_t*>(&h1);
        d4[i] = o;
    }
}

// Kernel B (launch 2): zero fp16 agg + convert X and all weights, ONE launch.
__global__ void prep_kernel(const float* __restrict__ X,
                            const float* __restrict__ Wm,
                            const float* __restrict__ Wih,
                            const float* __restrict__ Whh,
                            int exh4)
{
    int idx = blockIdx.x * blockDim.x + threadIdx.x;
    int stride = gridDim.x * blockDim.x;

    uint4* az = reinterpret_cast<uint4*>(g_agg_h);
    uint4 z = make_uint4(0, 0, 0, 0);
    int n8 = exh4 >> 1;
    for (int i = idx; i < n8; i += stride) az[i] = z;

    conv_seg(X,   g_x_h,   exh4,            idx, stride);
    conv_seg(Wm,  g_wm_h,  (H * H) / 4,     idx, stride);
    conv_seg(Wih, g_wih_h, (3 * H * H) / 4, idx, stride);
    conv_seg(Whh, g_whh_h, (3 * H * H) / 4, idx, stride);
}

// ============================================================================
// Kernel 1 (launch 3): message = relu(X16 @ Wm16^T + b); RED.F16x2 scatter.
// (byte-identical to round 16)
// ============================================================================
#define MS_STAGE_H 13824

__global__ __launch_bounds__(256, 3)
void msg_scatter_kernel(const void* __restrict__ eidx,
                        const float* __restrict__ bias,
                        int E)
{
    extern __shared__ uint32_t dsm[];
    __shared__ int dsts[128];

    const int tid  = threadIdx.x;
    const int lane = tid & 31;
    const int wid  = tid >> 5;
    const int wm   = wid & 3;
    const int wn   = wid >> 2;
    const int row0 = (int)(blockIdx.x >> 2) * 128;
    const int n0   = (int)(blockIdx.x & 3) * 64;
    const uint32_t sbase = (uint32_t)__cvta_generic_to_shared(dsm);

    const int sub  = lane >> 3;
    const int lrow = lane & 7;
    const int aoffB = ((sub & 1) * 8 + lrow) * 144 + (sub >> 1) * 16;
    const int boffB = ((sub >> 1) * 8 + lrow) * 144 + (sub & 1) * 16;

    if (tid < 128) {
        int r = row0 + tid;
        int d = -1;
        if (r < E) {
            d = g_idx_mode ? (int)((const long long*)eidx)[(size_t)E + r]
                           : ((const int*)eidx)[(size_t)E + r];
            if (d < 0 || d >= E) d = -1;
        }
        dsts[tid] = d;
    }

    auto load_stage = [&](int st, int k0) {
        uint32_t sb = sbase + st * (MS_STAGE_H * 2);
#pragma unroll
        for (int q = 0; q < 4; q++) {
            int f  = tid + q * 256;
            int r  = f >> 3;
            int ch = (f & 7) * 8;
            int gr = row0 + r;
            cp16(sb + (r * 72 + ch) * 2, g_x_h + (size_t)gr * H + k0 + ch, gr < E);
        }
#pragma unroll
        for (int q = 0; q < 2; q++) {
            int f  = tid + q * 256;
            int r  = f >> 3;
            int ch = (f & 7) * 8;
            cp16(sb + (9216 + r * 72 + ch) * 2,
                 g_wm_h + (size_t)(n0 + r) * H + k0 + ch, true);
        }
        cp_commit();
    };

    float acc[2][4][4];
#pragma unroll
    for (int i = 0; i < 2; i++)
#pragma unroll
        for (int j = 0; j < 4; j++)
#pragma unroll
            for (int k = 0; k < 4; k++) acc[i][j][k] = 0.0f;

    load_stage(0, 0);

    for (int kc = 0; kc < 4; kc++) {
        cp_wait<0>();
        __syncthreads();
        if (kc < 3) load_stage((kc + 1) & 1, (kc + 1) * 64);

        const uint32_t Au = sbase + ((kc & 1) * MS_STAGE_H) * 2;
        const uint32_t Bu = Au + 9216 * 2;

#pragma unroll
        for (int ks = 0; ks < 4; ks++) {
            int kb = ks * 32;
            uint32_t a[2][4], bb[2][4];
#pragma unroll
            for (int mi = 0; mi < 2; mi++)
                ldsm_x4(a[mi][0], a[mi][1], a[mi][2], a[mi][3],
                        Au + aoffB + (wm * 32 + mi * 16) * 144 + kb);
#pragma unroll
            for (int np = 0; np < 2; np++)
                ldsm_x4(bb[np][0], bb[np][1], bb[np][2], bb[np][3],
                        Bu + boffB + (wn * 32 + np * 16) * 144 + kb);
#pragma unroll
            for (int mi = 0; mi < 2; mi++)
#pragma unroll
                for (int np = 0; np < 2; np++) {
                    mma_f16(acc[mi][2 * np],     a[mi], bb[np][0], bb[np][1]);
                    mma_f16(acc[mi][2 * np + 1], a[mi], bb[np][2], bb[np][3]);
                }
        }
    }

#pragma unroll
    for (int mi = 0; mi < 2; mi++) {
#pragma unroll
        for (int half = 0; half < 2; half++) {
            int rl = wm * 32 + mi * 16 + (lane >> 2) + half * 8;
            int d  = dsts[rl];
            if (d < 0) continue;
            size_t base = (size_t)d * H;
#pragma unroll
            for (int ni = 0; ni < 4; ni++) {
                int col  = n0 + wn * 32 + ni * 8 + 2 * (lane & 3);
                float v0 = fmaxf(acc[mi][ni][half * 2 + 0] + __ldg(&bias[col]), 0.0f);
                float v1 = fmaxf(acc[mi][ni][half * 2 + 1] + __ldg(&bias[col + 1]), 0.0f);
                __half2 hv = __floats2half2_rn(v0, v1);
                atomicAdd(reinterpret_cast<__half2*>(&g_agg_h[base + col]), hv);
            }
        }
    }
}

// ============================================================================
// Kernel 2 (launch 4): GRU fused GEMMs. Mainloop identical to round 16.
// gbuf now fp16 with padded stride 200 halves (400B/row -> bank shift 4/row,
// conflict-free dump); epilogue 4-col vectorized (uint2 gbuf, float4 gmem).
// ============================================================================
#define GK_STAGE_H 23040
#define GB_STRIDE  200   // halves; 64*200*2 = 25.6KB aliases the 92KB ring

__global__ __launch_bounds__(384, 2)
void gru_kernel(const float* __restrict__ X,
                const float* __restrict__ bih,
                const float* __restrict__ bhh,
                float* __restrict__ out,
                int E)
{
    extern __shared__ uint32_t dsm[];
    __half* gbuf = reinterpret_cast<__half*>(dsm);

    const int tid  = threadIdx.x;
    const int lane = tid & 31;
    const int wid  = tid >> 5;
    const int wm   = wid & 1;
    const int g    = wid >> 1;
    const int row0 = (int)(blockIdx.x >> 3) * 64;
    const int n0   = (int)(blockIdx.x & 7) * 32;
    const uint32_t sbase = (uint32_t)__cvta_generic_to_shared(dsm);

    const int sub  = lane >> 3;
    const int lrow = lane & 7;
    const int aoffB = ((sub & 1) * 8 + lrow) * 144 + (sub >> 1) * 16;
    const int boffB = ((sub >> 1) * 8 + lrow) * 144 + (sub & 1) * 16;

    auto load_stage = [&](int st, int k0) {
        uint32_t sb = sbase + st * (GK_STAGE_H * 2);
        for (int f = tid; f < 1024; f += 384) {
            int which = f >> 9;
            int rem   = f & 511;
            int r     = rem >> 3;
            int ch    = (rem & 7) * 8;
            int gr    = row0 + r;
            const __half* src = which ? (g_x_h + (size_t)gr * H)
                                      : (g_agg_h + (size_t)gr * H);
            cp16(sb + ((which ? 4608 : 0) + r * 72 + ch) * 2, src + k0 + ch, gr < E);
        }
#pragma unroll
        for (int q = 0; q < 4; q++) {
            int f    = tid + q * 384;
            int g2   = f >> 8;
            int rem  = f & 255;
            int r    = rem >> 3;
            int ch   = (rem & 7) * 8;
            int gate = (g2 < 3) ? g2 : (g2 - 3);
            const __half* Wsrc = (g2 < 3) ? g_wih_h : g_whh_h;
            cp16(sb + (9216 + (g2 * 32 + r) * 72 + ch) * 2,
                 Wsrc + (size_t)(gate * H + n0 + r) * H + k0 + ch, true);
        }
        cp_commit();
    };

    float acc[2][4][4];
#pragma unroll
    for (int i = 0; i < 2; i++)
#pragma unroll
        for (int j = 0; j < 4; j++)
#pragma unroll
            for (int k = 0; k < 4; k++) acc[i][j][k] = 0.0f;

    load_stage(0, 0);

    for (int kc = 0; kc < 4; kc++) {
        cp_wait<0>();
        __syncthreads();
        if (kc < 3) load_stage((kc + 1) & 1, (kc + 1) * 64);

        const uint32_t Su = sbase + ((kc & 1) * GK_STAGE_H) * 2;
        const uint32_t Au = Su + ((g < 3) ? 0 : 4608) * 2;
        const uint32_t Bu = Su + 9216 * 2;

#pragma unroll
        for (int ks = 0; ks < 4; ks++) {
            int kb = ks * 32;
            uint32_t a[2][4], bb[2][4];
#pragma unroll
            for (int mi = 0; mi < 2; mi++)
                ldsm_x4(a[mi][0], a[mi][1], a[mi][2], a[mi][3],
                        Au + aoffB + (wm * 32 + mi * 16) * 144 + kb);
#pragma unroll
            for (int np = 0; np < 2; np++)
                ldsm_x4(bb[np][0], bb[np][1], bb[np][2], bb[np][3],
                        Bu + boffB + (g * 32 + np * 16) * 144 + kb);
#pragma unroll
            for (int mi = 0; mi < 2; mi++)
#pragma unroll
                for (int np = 0; np < 2; np++) {
                    mma_f16(acc[mi][2 * np],     a[mi], bb[np][0], bb[np][1]);
                    mma_f16(acc[mi][2 * np + 1], a[mi], bb[np][2], bb[np][3]);
                }
        }
    }

    __syncthreads();   // all warps done reading the ring before gbuf aliasing

    // ---- dump accumulators as fp16: gbuf[r][g*32 + c], stride 200 halves ----
#pragma unroll
    for (int mi = 0; mi < 2; mi++) {
        int r = wm * 32 + mi * 16 + (lane >> 2);
#pragma unroll
        for (int ni = 0; ni < 4; ni++) {
            int c = g * 32 + ni * 8 + 2 * (lane & 3);
            *reinterpret_cast<__half2*>(&gbuf[r * GB_STRIDE + c]) =
                __floats2half2_rn(acc[mi][ni][0], acc[mi][ni][1]);
            *reinterpret_cast<__half2*>(&gbuf[(r + 8) * GB_STRIDE + c]) =
                __floats2half2_rn(acc[mi][ni][2], acc[mi][ni][3]);
        }
    }
    __syncthreads();

    // ---- GRU gate math + output: 4 cols/iter (64 rows x 8 quads = 512) ----
    for (int idx = tid; idx < 64 * 8; idx += 384) {
        int r  = idx >> 3;
        int c  = (idx & 7) * 4;
        int gr = row0 + r;
        if (gr >= E) continue;
        int gc = n0 + c;
        const __half* gr_ = &gbuf[r * GB_STRIDE];

        // 6 gate pre-activation quads (4 halves each)
        uint2 uir = *reinterpret_cast<const uint2*>(gr_ + c);
        uint2 uiz = *reinterpret_cast<const uint2*>(gr_ + 32 + c);
        uint2 uin = *reinterpret_cast<const uint2*>(gr_ + 64 + c);
        uint2 uhr = *reinterpret_cast<const uint2*>(gr_ + 96 + c);
        uint2 uhz = *reinterpret_cast<const uint2*>(gr_ + 128 + c);
        uint2 uhn = *reinterpret_cast<const uint2*>(gr_ + 160 + c);

        float4 bir = *reinterpret_cast<const float4*>(bih + gc);
        float4 biz = *reinterpret_cast<const float4*>(bih + H + gc);
        float4 bin = *reinterpret_cast<const float4*>(bih + 2 * H + gc);
        float4 bhr = *reinterpret_cast<const float4*>(bhh + gc);
        float4 bhz = *reinterpret_cast<const float4*>(bhh + H + gc);
        float4 bhn = *reinterpret_cast<const float4*>(bhh + 2 * H + gc);

        float4 hp = *reinterpret_cast<const float4*>(X + (size_t)gr * H + gc);

        float2 ir0 = __half22float2(*reinterpret_cast<const __half2*>(&uir.x));
        float2 ir1 = __half22float2(*reinterpret_cast<const __half2*>(&uir.y));
        float2 iz0 = __half22float2(*reinterpret_cast<const __half2*>(&uiz.x));
        float2 iz1 = __half22float2(*reinterpret_cast<const __half2*>(&uiz.y));
        float2 in0 = __half22float2(*reinterpret_cast<const __half2*>(&uin.x));
        float2 in1 = __half22float2(*reinterpret_cast<const __half2*>(&uin.y));
        float2 hr0 = __half22float2(*reinterpret_cast<const __half2*>(&uhr.x));
        float2 hr1 = __half22float2(*reinterpret_cast<const __half2*>(&uhr.y));
        float2 hz0 = __half22float2(*reinterpret_cast<const __half2*>(&uhz.x));
        float2 hz1 = __half22float2(*reinterpret_cast<const __half2*>(&uhz.y));
        float2 hn0 = __half22float2(*reinterpret_cast<const __half2*>(&uhn.x));
        float2 hn1 = __half22float2(*reinterpret_cast<const __half2*>(&uhn.y));

        float4 o;
        {
            float rg = sigmoid_fast(ir0.x + bir.x + hr0.x + bhr.x);
            float z  = sigmoid_fast(iz0.x + biz.x + hz0.x + bhz.x);
            float n  = tanh_fast(in0.x + bin.x + rg * (hn0.x + bhn.x));
            o.x = (1.0f - z) * n + z * hp.x;
        }
        {
            float rg = sigmoid_fast(ir0.y + bir.y + hr0.y + bhr.y);
            float z  = sigmoid_fast(iz0.y + biz.y + hz0.y + bhz.y);
            float n  = tanh_fast(in0.y + bin.y + rg * (hn0.y + bhn.y));
            o.y = (1.0f - z) * n + z * hp.y;
        }
        {
            float rg = sigmoid_fast(ir1.x + bir.z + hr1.x + bhr.z);
            float z  = sigmoid_fast(iz1.x + biz.z + hz1.x + bhz.z);
            float n  = tanh_fast(in1.x + bin.z + rg * (hn1.x + bhn.z));
            o.z = (1.0f - z) * n + z * hp.z;
        }
        {
            float rg = sigmoid_fast(ir1.y + bir.w + hr1.y + bhr.w);
            float z  = sigmoid_fast(iz1.y + biz.w + hz1.y + bhz.w);
            float n  = tanh_fast(in1.y + bin.w + rg * (hn1.y + bhn.w));
            o.w = (1.0f - z) * n + z * hp.w;
        }
        *reinterpret_cast<float4*>(out + (size_t)gr * H + gc) = o;
    }
}

// ============================================================================
extern "C" void kernel_launch(void* const* d_in, const int* in_sizes, int n_in,
                              void* d_out, int out_size)
{
    const float* X   = (const float*)d_in[0];
    const void*  ei  = d_in[1];
    const float* Wm  = (const float*)d_in[2];
    const float* bm  = (const float*)d_in[3];
    const float* Wih = (const float*)d_in[4];
    const float* Whh = (const float*)d_in[5];
    const float* bih = (const float*)d_in[6];
    const float* bhh = (const float*)d_in[7];
    float*       out = (float*)d_out;

    int E = in_sizes[0] / H;

    cudaFuncSetAttribute(msg_scatter_kernel,
                         cudaFuncAttributeMaxDynamicSharedMemorySize, 2 * MS_STAGE_H * 2);
    cudaFuncSetAttribute(gru_kernel,
                         cudaFuncAttributeMaxDynamicSharedMemorySize, 2 * GK_STAGE_H * 2);

    detect_idx_kernel<<<1, 256>>>((const int*)ei);                        // 1
    prep_kernel<<<4096, 256>>>(X, Wm, Wih, Whh, (E * H) / 4);             // 2

    int mrows = (E + 127) / 128;
    msg_scatter_kernel<<<mrows * 4, 256, 2 * MS_STAGE_H * 2>>>(ei, bm, E); // 3

    int grows = (E + 63) / 64;
    gru_kernel<<<grows * 8, 384, 2 * GK_STAGE_H * 2>>>(X, bih, bhh, out, E); // 4
}